// round 1
// baseline (speedup 1.0000x reference)
#include <cuda_runtime.h>
#include <math.h>

typedef unsigned long long ull;

#define TT    2048
#define NH    32
#define NKV   8
#define HD    128
#define NSALT 512
#define NSEG  4
#define SMAXK 512
#define SCALE_F 0.08838834764831845f

// ---------------- scratch (device globals: allocation-free) ----------------
__device__ float g_S[(size_t)TT * NH * SMAXK];      // scores -> probabilities
__device__ float g_vdelta[NSALT * NKV * HD];
__device__ int   g_idx[NSALT];
__device__ int   g_cu[NSEG + 1];
__device__ int   g_salpos[TT];
__device__ int   g_salst[NSEG];
__device__ int   g_salcnt[NSEG];
__device__ int   g_rowL[TT];

// ---------------- helpers ----------------
__device__ __forceinline__ float2 unpk(ull p) {
    float2 r;
    asm("mov.b64 {%0, %1}, %2;" : "=f"(r.x), "=f"(r.y) : "l"(p));
    return r;
}

// 128x128 output tile, 32-deep K chunk. 256 threads, 8x8 per thread.
// Accumulators are f32x2 pairs along the N dimension (FFMA2: 2x fp32 rate).
__device__ __forceinline__ void mma_step(const float (*As)[128], const float (*Bs)[128],
                                         ull acc[8][4], int ty, int tx) {
#pragma unroll
    for (int kk = 0; kk < 32; kk++) {
        float4 a0 = *(const float4*)&As[kk][ty * 8];
        float4 a1 = *(const float4*)&As[kk][ty * 8 + 4];
        float4 b0 = *(const float4*)&Bs[kk][tx * 8];
        float4 b1 = *(const float4*)&Bs[kk][tx * 8 + 4];
        ull b2[4];
        b2[0] = ((const ull*)&b0)[0];
        b2[1] = ((const ull*)&b0)[1];
        b2[2] = ((const ull*)&b1)[0];
        b2[3] = ((const ull*)&b1)[1];
        float av[8] = {a0.x, a0.y, a0.z, a0.w, a1.x, a1.y, a1.z, a1.w};
#pragma unroll
        for (int u = 0; u < 8; u++) {
            ull a2;
            asm("mov.b64 %0, {%1, %1};" : "=l"(a2) : "f"(av[u]));
#pragma unroll
            for (int v = 0; v < 4; v++)
                asm("fma.rn.f32x2 %0, %1, %2, %0;" : "+l"(acc[u][v]) : "l"(a2), "l"(b2[v]));
        }
    }
}

// ---------------- K0a: decode indices (int32/int64 robust), segment tables ----------------
__global__ void k_prep(const void* idx_raw, const void* cu_raw) {
    const int* i32 = (const int*)idx_raw;
    const int* c32 = (const int*)cu_raw;
    // int64 storage => odd 32-bit words (high halves) are 0 for values < 2^31.
    // int32 storage => word[1] is idx[1] (=4) / cu[1] (=512), nonzero.
    const bool idx64 = (i32[1] == 0);
    const bool cu64  = (c32[1] == 0);
    const int t = threadIdx.x;

    for (int i = t; i < NSALT; i += 256)
        g_idx[i] = idx64 ? (int)((const long long*)idx_raw)[i] : i32[i];
    if (t <= NSEG)
        g_cu[t] = cu64 ? (int)((const long long*)cu_raw)[t] : c32[t];
    for (int i = t; i < TT; i += 256) g_salpos[i] = -1;
    __syncthreads();
    for (int i = t; i < NSALT; i += 256) g_salpos[g_idx[i]] = i;
    if (t == 0) {
        for (int s = 0; s < NSEG; s++) {
            int a = 0;
            while (a < NSALT && g_idx[a] < g_cu[s]) a++;
            int b = a;
            while (b < NSALT && g_idx[b] < g_cu[s + 1]) b++;
            g_salst[s] = a;
            g_salcnt[s] = b - a;
        }
    }
    for (int i = t; i < TT; i += 256) {
        int s = 0;
        while (s < NSEG - 1 && i >= g_cu[s + 1]) s++;
        g_rowL[i] = g_cu[s + 1] - g_cu[s];
    }
}

// ---------------- K0b: v_delta = v - v_cache[idx] ----------------
__global__ void k_vdelta(const float* __restrict__ v, const float* __restrict__ vc) {
    int sal = blockIdx.x;
    int gi = g_idx[sal];
    int e = threadIdx.x * 4;
    float4 a = *(const float4*)(v + (size_t)sal * NKV * HD + e);
    float4 b = *(const float4*)(vc + (size_t)gi * NKV * HD + e);
    float4 d = make_float4(a.x - b.x, a.y - b.y, a.z - b.z, a.w - b.w);
    *(float4*)(g_vdelta + (size_t)sal * NKV * HD + e) = d;
}

// ---------------- K1: S = scale * Q K^T per (segment, kv-head) ----------------
// M rows = (i_local, hh) pairs (4 heads per kv head), N = keys in segment.
__global__ void __launch_bounds__(256) k_qk(const float* __restrict__ q, const float* __restrict__ kmat) {
    const int s = blockIdx.z >> 3, g = blockIdx.z & 7;
    const int s0 = g_cu[s];
    const int L = g_cu[s + 1] - s0;
    const int mBase = blockIdx.y * 128;
    const int nBase = blockIdx.x * 128;
    if (mBase >= 4 * L || nBase >= L) return;

    __shared__ float As[32][128];
    __shared__ float Bs[32][128];
    const int t = threadIdx.x;
    const int tx = t & 15, ty = t >> 4;

    ull acc[8][4];
#pragma unroll
    for (int u = 0; u < 8; u++)
#pragma unroll
        for (int v = 0; v < 4; v++) acc[u][v] = 0ull;

    for (int k0 = 0; k0 < HD; k0 += 32) {
#pragma unroll
        for (int it = 0; it < 4; it++) {
            int m = (t >> 3) + 32 * it;
            int kv = (t & 7) * 4;
            int mm = mBase + m;
            int iloc = mm >> 2, hh = mm & 3;
            float4 va = make_float4(0.f, 0.f, 0.f, 0.f);
            if (iloc < L)
                va = *(const float4*)(q + ((size_t)(s0 + iloc) * NH + 4 * g + hh) * HD + k0 + kv);
            As[kv + 0][m] = va.x; As[kv + 1][m] = va.y; As[kv + 2][m] = va.z; As[kv + 3][m] = va.w;
            int jg = nBase + m;
            float4 vb = make_float4(0.f, 0.f, 0.f, 0.f);
            if (jg < L)
                vb = *(const float4*)(kmat + ((size_t)(s0 + jg) * NKV + g) * HD + k0 + kv);
            Bs[kv + 0][m] = vb.x; Bs[kv + 1][m] = vb.y; Bs[kv + 2][m] = vb.z; Bs[kv + 3][m] = vb.w;
        }
        __syncthreads();
        mma_step(As, Bs, acc, ty, tx);
        __syncthreads();
    }

#pragma unroll
    for (int u = 0; u < 8; u++) {
        int mm = mBase + ty * 8 + u;
        int iloc = mm >> 2, hh = mm & 3;
        if (iloc >= L) continue;
        size_t row = ((size_t)(s0 + iloc) * NH + 4 * g + hh) * SMAXK;
        float o[8];
#pragma unroll
        for (int v = 0; v < 4; v++) {
            float2 f = unpk(acc[u][v]);
            o[2 * v] = f.x * SCALE_F;
            o[2 * v + 1] = f.y * SCALE_F;
        }
        int c0 = nBase + tx * 8;
        if (c0 + 7 < L) {
            *(float4*)(g_S + row + c0)     = make_float4(o[0], o[1], o[2], o[3]);
            *(float4*)(g_S + row + c0 + 4) = make_float4(o[4], o[5], o[6], o[7]);
        } else {
            for (int c = 0; c < 8; c++)
                if (c0 + c < L) g_S[row + c0 + c] = o[c];
        }
    }
}

// ---------------- K2: row softmax in place (one warp per (i,h) row) ----------------
__global__ void __launch_bounds__(256) k_softmax() {
    int r = blockIdx.x * 8 + (threadIdx.x >> 5);
    int lane = threadIdx.x & 31;
    int i = r >> 5;  // r / NH
    int L = g_rowL[i];
    float* row = g_S + (size_t)r * SMAXK;
    float vals[16];
    float m = -1e30f;
#pragma unroll
    for (int u = 0; u < 16; u++) {
        int j = lane + 32 * u;
        vals[u] = (j < L) ? row[j] : -1e30f;
        m = fmaxf(m, vals[u]);
    }
#pragma unroll
    for (int o = 16; o; o >>= 1) m = fmaxf(m, __shfl_xor_sync(0xffffffffu, m, o));
    float sum = 0.f;
#pragma unroll
    for (int u = 0; u < 16; u++) {
        int j = lane + 32 * u;
        float e = (j < L) ? __expf(vals[u] - m) : 0.f;
        vals[u] = e;
        sum += e;
    }
#pragma unroll
    for (int o = 16; o; o >>= 1) sum += __shfl_xor_sync(0xffffffffu, sum, o);
    float inv = 1.f / sum;
#pragma unroll
    for (int u = 0; u < 16; u++) {
        int j = lane + 32 * u;
        if (j < L) row[j] = vals[u] * inv;
    }
}

// ---------------- K3: out = c_cache + P[:, salient] @ v_delta ----------------
__global__ void __launch_bounds__(256) k_delta(const float* __restrict__ cc, float* __restrict__ outc) {
    const int s = blockIdx.z >> 3, g = blockIdx.z & 7;
    const int s0 = g_cu[s];
    const int L = g_cu[s + 1] - s0;
    const int salst = g_salst[s], salcnt = g_salcnt[s];
    const int mBase = blockIdx.y * 128;
    if (mBase >= 4 * L) return;

    __shared__ float As[32][128];
    __shared__ float Bs[32][128];
    const int t = threadIdx.x;
    const int tx = t & 15, ty = t >> 4;

    ull acc[8][4];
#pragma unroll
    for (int u = 0; u < 8; u++)
#pragma unroll
        for (int v = 0; v < 4; v++) acc[u][v] = 0ull;

    for (int k0 = 0; k0 < salcnt; k0 += 32) {
#pragma unroll
        for (int it = 0; it < 4; it++) {
            int m = (t >> 3) + 32 * it;
            int kv = (t & 7) * 4;
            int mm = mBase + m;
            int iloc = mm >> 2, hh = mm & 3;
            size_t rowbase = ((size_t)(s0 + iloc) * NH + 4 * g + hh) * SMAXK;
#pragma unroll
            for (int c = 0; c < 4; c++) {
                int ks = k0 + kv + c;
                float va = 0.f;
                if (iloc < L && ks < salcnt) {
                    int jloc = g_idx[salst + ks] - s0;
                    va = g_S[rowbase + jloc];
                }
                As[kv + c][m] = va;
            }
            int ks2 = (t >> 5) + 8 * it;
            int n4 = (t & 31) * 4;
            float4 vb = make_float4(0.f, 0.f, 0.f, 0.f);
            if (k0 + ks2 < salcnt)
                vb = *(const float4*)(g_vdelta + ((size_t)(salst + k0 + ks2) * NKV + g) * HD + n4);
            *(float4*)&Bs[ks2][n4] = vb;
        }
        __syncthreads();
        mma_step(As, Bs, acc, ty, tx);
        __syncthreads();
    }

#pragma unroll
    for (int u = 0; u < 8; u++) {
        int mm = mBase + ty * 8 + u;
        int iloc = mm >> 2, hh = mm & 3;
        if (iloc >= L) continue;
        size_t ob = ((size_t)(s0 + iloc) * NH + 4 * g + hh) * HD + tx * 8;
        float4 cv0 = *(const float4*)(cc + ob);
        float4 cv1 = *(const float4*)(cc + ob + 4);
        float2 f0 = unpk(acc[u][0]), f1 = unpk(acc[u][1]);
        float2 f2 = unpk(acc[u][2]), f3 = unpk(acc[u][3]);
        *(float4*)(outc + ob)     = make_float4(cv0.x + f0.x, cv0.y + f0.y, cv0.z + f1.x, cv0.w + f1.y);
        *(float4*)(outc + ob + 4) = make_float4(cv1.x + f2.x, cv1.y + f2.y, cv1.z + f3.x, cv1.w + f3.y);
    }
}

// ---------------- K4: salient rows: out = P @ v_cache_new (overwrite) ----------------
__global__ void __launch_bounds__(256) k_osal(const float* __restrict__ v, const float* __restrict__ vc,
                                              float* __restrict__ outc) {
    const int s = blockIdx.z >> 3, g = blockIdx.z & 7;
    const int s0 = g_cu[s];
    const int L = g_cu[s + 1] - s0;
    const int salst = g_salst[s], salcnt = g_salcnt[s];
    const int mBase = blockIdx.y * 128;
    if (mBase >= 4 * salcnt) return;

    __shared__ float As[32][128];
    __shared__ float Bs[32][128];
    const int t = threadIdx.x;
    const int tx = t & 15, ty = t >> 4;

    ull acc[8][4];
#pragma unroll
    for (int u = 0; u < 8; u++)
#pragma unroll
        for (int v2 = 0; v2 < 4; v2++) acc[u][v2] = 0ull;

    for (int k0 = 0; k0 < L; k0 += 32) {
#pragma unroll
        for (int it = 0; it < 4; it++) {
            int m = (t >> 3) + 32 * it;
            int j4 = (t & 7) * 4;
            int mm = mBase + m;
            int sq = mm >> 2, hh = mm & 3;
            float4 va = make_float4(0.f, 0.f, 0.f, 0.f);
            if (sq < salcnt) {
                int gi = g_idx[salst + sq];
                va = *(const float4*)(g_S + ((size_t)gi * NH + 4 * g + hh) * SMAXK + k0 + j4);
            }
            As[j4 + 0][m] = va.x; As[j4 + 1][m] = va.y; As[j4 + 2][m] = va.z; As[j4 + 3][m] = va.w;

            int j = (t >> 5) + 8 * it;
            int n4 = (t & 31) * 4;
            float4 vb = make_float4(0.f, 0.f, 0.f, 0.f);
            if (k0 + j < L) {
                int jg = s0 + k0 + j;
                int sp = g_salpos[jg];
                const float* src = (sp >= 0) ? (v + ((size_t)sp * NKV + g) * HD)
                                             : (vc + ((size_t)jg * NKV + g) * HD);
                vb = *(const float4*)(src + n4);
            }
            *(float4*)&Bs[j][n4] = vb;
        }
        __syncthreads();
        mma_step(As, Bs, acc, ty, tx);
        __syncthreads();
    }

#pragma unroll
    for (int u = 0; u < 8; u++) {
        int mm = mBase + ty * 8 + u;
        int sq = mm >> 2, hh = mm & 3;
        if (sq >= salcnt) continue;
        int gi = g_idx[salst + sq];
        size_t ob = ((size_t)gi * NH + 4 * g + hh) * HD + tx * 8;
        float2 f0 = unpk(acc[u][0]), f1 = unpk(acc[u][1]);
        float2 f2 = unpk(acc[u][2]), f3 = unpk(acc[u][3]);
        *(float4*)(outc + ob)     = make_float4(f0.x, f0.y, f1.x, f1.y);
        *(float4*)(outc + ob + 4) = make_float4(f2.x, f2.y, f3.x, f3.y);
    }
}

// ---------------- K5: per-row cosine similarity ----------------
__global__ void __launch_bounds__(256) k_cos(const float* __restrict__ cc, const float* __restrict__ outc,
                                             float* __restrict__ cosv) {
    __shared__ float sh[3][256];
    size_t base = (size_t)blockIdx.x * (NH * HD);
    const float4* a4 = (const float4*)(cc + base);
    const float4* b4 = (const float4*)(outc + base);
    float ab = 0.f, aa = 0.f, bb = 0.f;
    for (int j = threadIdx.x; j < (NH * HD) / 4; j += 256) {
        float4 x = a4[j], y = b4[j];
        ab += x.x * y.x + x.y * y.y + x.z * y.z + x.w * y.w;
        aa += x.x * x.x + x.y * x.y + x.z * x.z + x.w * x.w;
        bb += y.x * y.x + y.y * y.y + y.z * y.z + y.w * y.w;
    }
    sh[0][threadIdx.x] = ab; sh[1][threadIdx.x] = aa; sh[2][threadIdx.x] = bb;
    __syncthreads();
    for (int o = 128; o; o >>= 1) {
        if (threadIdx.x < o) {
            sh[0][threadIdx.x] += sh[0][threadIdx.x + o];
            sh[1][threadIdx.x] += sh[1][threadIdx.x + o];
            sh[2][threadIdx.x] += sh[2][threadIdx.x + o];
        }
        __syncthreads();
    }
    if (threadIdx.x == 0)
        cosv[blockIdx.x] = sh[0][0] / (sqrtf(sh[1][0]) * sqrtf(sh[2][0]) + 1e-8f);
}

// ---------------- launch ----------------
extern "C" void kernel_launch(void* const* d_in, const int* in_sizes, int n_in,
                              void* d_out, int out_size) {
    const float* q       = (const float*)d_in[0];
    const float* k       = (const float*)d_in[1];
    const float* v       = (const float*)d_in[2];
    const float* v_cache = (const float*)d_in[3];
    const float* c_cache = (const float*)d_in[4];
    const void*  idx     = d_in[5];
    const void*  cu      = d_in[6];

    float* outc = (float*)d_out;
    float* cosv = outc + (size_t)(out_size - TT);  // [2048*32*128 new_c][2048 cos_sim]

    k_prep<<<1, 256>>>(idx, cu);
    k_vdelta<<<NSALT, 256>>>(v, v_cache);
    k_qk<<<dim3(SMAXK / 128, (4 * SMAXK) / 128, NSEG * NKV), 256>>>(q, k);
    k_softmax<<<(TT * NH) / 8, 256>>>();
    k_delta<<<dim3(1, (4 * SMAXK) / 128, NSEG * NKV), 256>>>(c_cache, outc);
    k_osal<<<dim3(1, (4 * (NSALT / NSEG)) / 128, NSEG * NKV), 256>>>(v, v_cache, outc);
    k_cos<<<TT, 256>>>(c_cache, outc, cosv);
}

// round 4
// speedup vs baseline: 1.1767x; 1.1767x over previous
#include <cuda_runtime.h>
#include <cuda_bf16.h>
#include <math.h>
#include <stdint.h>

typedef unsigned long long ull;

#define TT    2048
#define NH    32
#define NKV   8
#define HD    128
#define NSALT 512
#define NSEG  4
#define SMAXK 512
#define SCALE_F 0.08838834764831845f

// ---------------- scratch (device globals: allocation-free) ----------------
__device__ float g_S[(size_t)TT * NH * SMAXK];      // unnormalized exp(scores)
__device__ float g_part[(size_t)TT * NH * 16];      // per-(row, ntile, nwarp) partial sums
__device__ float g_vdelta[NSALT * NKV * HD];
__device__ __nv_bfloat16 g_qhi[(size_t)TT * NH * HD];
__device__ __nv_bfloat16 g_qlo[(size_t)TT * NH * HD];
__device__ __nv_bfloat16 g_khi[(size_t)TT * NKV * HD];
__device__ __nv_bfloat16 g_klo[(size_t)TT * NKV * HD];
__device__ int   g_idx[NSALT];
__device__ int   g_cu[NSEG + 1];
__device__ int   g_salpos[TT];
__device__ int   g_salst[NSEG];
__device__ int   g_salcnt[NSEG];

// ---------------- helpers ----------------
__device__ __forceinline__ uint32_t smem_to_u32(const void* p) {
    uint32_t a;
    asm("{ .reg .u64 t; cvta.to.shared.u64 t, %1; cvt.u32.u64 %0, t; }" : "=r"(a) : "l"(p));
    return a;
}

__device__ __forceinline__ void ldsm4(uint32_t* r, uint32_t addr) {
    asm volatile("ldmatrix.sync.aligned.m8n8.x4.shared.b16 {%0,%1,%2,%3}, [%4];"
        : "=r"(r[0]), "=r"(r[1]), "=r"(r[2]), "=r"(r[3]) : "r"(addr));
}

__device__ __forceinline__ void mma16816(float* c, const uint32_t* a, uint32_t b0, uint32_t b1) {
    asm volatile("mma.sync.aligned.m16n8k16.row.col.f32.bf16.bf16.f32 "
        "{%0,%1,%2,%3}, {%4,%5,%6,%7}, {%8,%9}, {%0,%1,%2,%3};"
        : "+f"(c[0]), "+f"(c[1]), "+f"(c[2]), "+f"(c[3])
        : "r"(a[0]), "r"(a[1]), "r"(a[2]), "r"(a[3]), "r"(b0), "r"(b1));
}

__device__ __forceinline__ float2 unpk(ull p) {
    float2 r;
    asm("mov.b64 {%0, %1}, %2;" : "=f"(r.x), "=f"(r.y) : "l"(p));
    return r;
}

// FFMA2 microkernel for the PV GEMMs (fp32, packed f32x2)
__device__ __forceinline__ void mma_step(const float (*As)[128], const float (*Bs)[128],
                                         ull acc[8][4], int ty, int tx) {
#pragma unroll
    for (int kk = 0; kk < 32; kk++) {
        float4 a0 = *(const float4*)&As[kk][ty * 8];
        float4 a1 = *(const float4*)&As[kk][ty * 8 + 4];
        float4 b0 = *(const float4*)&Bs[kk][tx * 8];
        float4 b1 = *(const float4*)&Bs[kk][tx * 8 + 4];
        ull b2[4];
        b2[0] = ((const ull*)&b0)[0];
        b2[1] = ((const ull*)&b0)[1];
        b2[2] = ((const ull*)&b1)[0];
        b2[3] = ((const ull*)&b1)[1];
        float av[8] = {a0.x, a0.y, a0.z, a0.w, a1.x, a1.y, a1.z, a1.w};
#pragma unroll
        for (int u = 0; u < 8; u++) {
            ull a2;
            asm("mov.b64 %0, {%1, %1};" : "=l"(a2) : "f"(av[u]));
#pragma unroll
            for (int v = 0; v < 4; v++)
                asm("fma.rn.f32x2 %0, %1, %2, %0;" : "+l"(acc[u][v]) : "l"(a2), "l"(b2[v]));
        }
    }
}

// row-sum reconstruction: inv = 1 / sum(all 16 (ntile, nwarp) partials)
__device__ __forceinline__ float row_inv(size_t id, int L) {
    float rs = 0.f;
#pragma unroll
    for (int p = 0; p < 16; p++)
        if ((p >> 2) * 128 < L) rs += g_part[id * 16 + p];
    return 1.f / rs;
}

// ---------------- K0a: decode indices, segment tables ----------------
__global__ void k_prep(const void* idx_raw, const void* cu_raw) {
    const int* i32 = (const int*)idx_raw;
    const int* c32 = (const int*)cu_raw;
    const bool idx64 = (i32[1] == 0);
    const bool cu64  = (c32[1] == 0);
    const int t = threadIdx.x;

    for (int i = t; i < NSALT; i += 256)
        g_idx[i] = idx64 ? (int)((const long long*)idx_raw)[i] : i32[i];
    if (t <= NSEG)
        g_cu[t] = cu64 ? (int)((const long long*)cu_raw)[t] : c32[t];
    for (int i = t; i < TT; i += 256) g_salpos[i] = -1;
    __syncthreads();
    for (int i = t; i < NSALT; i += 256) g_salpos[g_idx[i]] = i;
    if (t == 0) {
        for (int s = 0; s < NSEG; s++) {
            int a = 0;
            while (a < NSALT && g_idx[a] < g_cu[s]) a++;
            int b = a;
            while (b < NSALT && g_idx[b] < g_cu[s + 1]) b++;
            g_salst[s] = a;
            g_salcnt[s] = b - a;
        }
    }
}

// ---------------- K0b: v_delta = v - v_cache[idx] ----------------
__global__ void k_vdelta(const float* __restrict__ v, const float* __restrict__ vc) {
    int sal = blockIdx.x;
    int gi = g_idx[sal];
    int e = threadIdx.x * 4;
    float4 a = *(const float4*)(v + (size_t)sal * NKV * HD + e);
    float4 b = *(const float4*)(vc + (size_t)gi * NKV * HD + e);
    *(float4*)(g_vdelta + (size_t)sal * NKV * HD + e) =
        make_float4(a.x - b.x, a.y - b.y, a.z - b.z, a.w - b.w);
}

// ---------------- K0c: fp32 -> bf16 hi/lo split of Q and K ----------------
__global__ void k_cvt(const float* __restrict__ q, const float* __restrict__ kk) {
    const int nq4 = TT * NH * HD / 4;
    int i = blockIdx.x * 256 + threadIdx.x;
    float4 x;
    __nv_bfloat162 *h2, *l2;
    if (i < nq4) {
        x = ((const float4*)q)[i];
        h2 = (__nv_bfloat162*)g_qhi + 2 * (size_t)i;
        l2 = (__nv_bfloat162*)g_qlo + 2 * (size_t)i;
    } else {
        int j = i - nq4;
        x = ((const float4*)kk)[j];
        h2 = (__nv_bfloat162*)g_khi + 2 * (size_t)j;
        l2 = (__nv_bfloat162*)g_klo + 2 * (size_t)j;
    }
    __nv_bfloat162 a = __float22bfloat162_rn(make_float2(x.x, x.y));
    __nv_bfloat162 b = __float22bfloat162_rn(make_float2(x.z, x.w));
    __nv_bfloat162 al = __float22bfloat162_rn(make_float2(x.x - __low2float(a), x.y - __high2float(a)));
    __nv_bfloat162 bl = __float22bfloat162_rn(make_float2(x.z - __low2float(b), x.w - __high2float(b)));
    h2[0] = a; h2[1] = b; l2[0] = al; l2[1] = bl;
}

// ---------------- K1: fused QK^T (HMMA bf16 3-pass) + exp + partial row sums ----------------
// CTA tile 128(m) x 128(n), K = HD = 128 resident in smem. 8 warps = 2(m) x 4(n),
// warp tile 64x32. Smem: Ah | Al | Bh | Bl, 32KB each, 16B-chunk XOR swizzle.
__global__ void __launch_bounds__(256, 1) k_qk_hmma() {
    extern __shared__ char dsm[];
    const int s = blockIdx.z >> 3, g = blockIdx.z & 7;
    const int s0 = g_cu[s];
    const int L = g_cu[s + 1] - s0;
    const int mBase = blockIdx.y * 128;
    const int nBase = blockIdx.x * 128;
    if (mBase >= 4 * L || nBase >= L) return;

    const int tid = threadIdx.x, wid = tid >> 5, lane = tid & 31;
    const uint32_t sb = smem_to_u32(dsm);

    // ---- global -> smem, swizzled: chunk' = ch ^ (row & 7), 16B chunks, 256B rows
    for (int idx = tid; idx < 2048; idx += 256) {
        int r = idx >> 4, ch = idx & 15;
        uint32_t d = (uint32_t)(r * 256) + (((uint32_t)(ch ^ (r & 7))) << 4);
        int mm = mBase + r, iloc = mm >> 2, hh = mm & 3;
        uint4 vh = make_uint4(0, 0, 0, 0), vl = make_uint4(0, 0, 0, 0);
        if (iloc < L) {
            size_t o = ((size_t)(s0 + iloc) * NH + 4 * g + hh) * HD + ch * 8;
            vh = *(const uint4*)(g_qhi + o);
            vl = *(const uint4*)(g_qlo + o);
        }
        *(uint4*)(dsm + d) = vh;
        *(uint4*)(dsm + 32768 + d) = vl;
        int jg = nBase + r;
        uint4 wh = make_uint4(0, 0, 0, 0), wl = make_uint4(0, 0, 0, 0);
        if (jg < L) {
            size_t o = ((size_t)(s0 + jg) * NKV + g) * HD + ch * 8;
            wh = *(const uint4*)(g_khi + o);
            wl = *(const uint4*)(g_klo + o);
        }
        *(uint4*)(dsm + 65536 + d) = wh;
        *(uint4*)(dsm + 98304 + d) = wl;
    }
    __syncthreads();

    const int wm = wid >> 2, wn = wid & 3;
    float acc[4][4][4];
#pragma unroll
    for (int a = 0; a < 4; a++)
#pragma unroll
        for (int b = 0; b < 4; b++)
#pragma unroll
            for (int c = 0; c < 4; c++) acc[a][b][c] = 0.f;

    // ldmatrix address precompute
    uint32_t a_ad[4], a_rx[4];
#pragma unroll
    for (int mf = 0; mf < 4; mf++) {
        int row = wm * 64 + mf * 16 + (lane & 15);
        a_ad[mf] = sb + row * 256;
        a_rx[mf] = ((uint32_t)(row & 7)) << 4;
    }
    const int achunk = (lane >> 4);        // 0/1 -> k halves
    uint32_t b_ad[2], b_rx[2];
#pragma unroll
    for (int bg = 0; bg < 2; bg++) {
        int n = wn * 32 + bg * 16 + (lane & 7) + ((lane >> 4) << 3);
        b_ad[bg] = sb + 65536 + n * 256;
        b_rx[bg] = ((uint32_t)(n & 7)) << 4;
    }
    const int bchunk = (lane >> 3) & 1;

#pragma unroll
    for (int ks = 0; ks < 8; ks++) {
        uint32_t ah[4][4], al[4][4];
#pragma unroll
        for (int mf = 0; mf < 4; mf++) {
            uint32_t coff = (((uint32_t)(ks * 2 + achunk)) << 4) ^ a_rx[mf];
            ldsm4(ah[mf], a_ad[mf] + coff);
            ldsm4(al[mf], a_ad[mf] + 32768 + coff);
        }
        uint32_t bh[2][4], bl[2][4];
#pragma unroll
        for (int bg = 0; bg < 2; bg++) {
            uint32_t coff = (((uint32_t)(ks * 2 + bchunk)) << 4) ^ b_rx[bg];
            ldsm4(bh[bg], b_ad[bg] + coff);
            ldsm4(bl[bg], b_ad[bg] + 32768 + coff);
        }
#pragma unroll
        for (int mf = 0; mf < 4; mf++)
#pragma unroll
            for (int nf = 0; nf < 4; nf++) {
                int bg = nf >> 1, sel = (nf & 1) * 2;
                mma16816(acc[mf][nf], ah[mf], bh[bg][sel], bh[bg][sel + 1]);
                mma16816(acc[mf][nf], ah[mf], bl[bg][sel], bl[bg][sel + 1]);
                mma16816(acc[mf][nf], al[mf], bh[bg][sel], bh[bg][sel + 1]);
            }
    }

    // ---- epilogue: exp, store unnormalized P, per-(row, ntile, nwarp) partial sums
#pragma unroll
    for (int mf = 0; mf < 4; mf++) {
        int mr0 = mBase + wm * 64 + mf * 16 + (lane >> 2);
        int mr1 = mr0 + 8;
        int il0 = mr0 >> 2, h0 = mr0 & 3;
        int il1 = mr1 >> 2, h1 = mr1 & 3;
        bool ok0 = il0 < L, ok1 = il1 < L;
        size_t id0 = (size_t)(s0 + il0) * NH + 4 * g + h0;
        size_t id1 = (size_t)(s0 + il1) * NH + 4 * g + h1;
        float s0v = 0.f, s1v = 0.f;
#pragma unroll
        for (int nf = 0; nf < 4; nf++) {
            int col = nBase + wn * 32 + nf * 8 + (lane & 3) * 2;
            float* c = acc[mf][nf];
            float e0 = 0.f, e1 = 0.f, e2 = 0.f, e3 = 0.f;
            if (ok0 && col < L)     e0 = __expf(c[0] * SCALE_F);
            if (ok0 && col + 1 < L) e1 = __expf(c[1] * SCALE_F);
            if (ok1 && col < L)     e2 = __expf(c[2] * SCALE_F);
            if (ok1 && col + 1 < L) e3 = __expf(c[3] * SCALE_F);
            s0v += e0 + e1;
            s1v += e2 + e3;
            if (ok0) {
                if (col + 1 < L) *(float2*)(g_S + id0 * SMAXK + col) = make_float2(e0, e1);
                else if (col < L) g_S[id0 * SMAXK + col] = e0;
            }
            if (ok1) {
                if (col + 1 < L) *(float2*)(g_S + id1 * SMAXK + col) = make_float2(e2, e3);
                else if (col < L) g_S[id1 * SMAXK + col] = e2;
            }
        }
        s0v += __shfl_xor_sync(0xffffffffu, s0v, 1);
        s0v += __shfl_xor_sync(0xffffffffu, s0v, 2);
        s1v += __shfl_xor_sync(0xffffffffu, s1v, 1);
        s1v += __shfl_xor_sync(0xffffffffu, s1v, 2);
        if ((lane & 3) == 0) {
            int slot = blockIdx.x * 4 + wn;   // private per (ntile, nwarp)
            if (ok0) g_part[id0 * 16 + slot] = s0v;
            if (ok1) g_part[id1 * 16 + slot] = s1v;
        }
    }
}

// ---------------- K3: out = c_cache + inv * (E[:, salient] @ v_delta) ----------------
__global__ void __launch_bounds__(256) k_delta(const float* __restrict__ cc, float* __restrict__ outc) {
    const int s = blockIdx.z >> 3, g = blockIdx.z & 7;
    const int s0 = g_cu[s];
    const int L = g_cu[s + 1] - s0;
    const int salst = g_salst[s], salcnt = g_salcnt[s];
    const int mBase = blockIdx.y * 128;
    if (mBase >= 4 * L) return;

    __shared__ float As[32][128];
    __shared__ float Bs[32][128];
    const int t = threadIdx.x;
    const int tx = t & 15, ty = t >> 4;

    ull acc[8][4];
#pragma unroll
    for (int u = 0; u < 8; u++)
#pragma unroll
        for (int v = 0; v < 4; v++) acc[u][v] = 0ull;

    for (int k0 = 0; k0 < salcnt; k0 += 32) {
#pragma unroll
        for (int it = 0; it < 4; it++) {
            int m = (t >> 3) + 32 * it;
            int kv = (t & 7) * 4;
            int mm = mBase + m;
            int iloc = mm >> 2, hh = mm & 3;
            size_t rowbase = ((size_t)(s0 + iloc) * NH + 4 * g + hh) * SMAXK;
#pragma unroll
            for (int c = 0; c < 4; c++) {
                int ks = k0 + kv + c;
                float va = 0.f;
                if (iloc < L && ks < salcnt) {
                    int jloc = g_idx[salst + ks] - s0;
                    va = g_S[rowbase + jloc];
                }
                As[kv + c][m] = va;
            }
            int ks2 = (t >> 5) + 8 * it;
            int n4 = (t & 31) * 4;
            float4 vb = make_float4(0.f, 0.f, 0.f, 0.f);
            if (k0 + ks2 < salcnt)
                vb = *(const float4*)(g_vdelta + ((size_t)(salst + k0 + ks2) * NKV + g) * HD + n4);
            *(float4*)&Bs[ks2][n4] = vb;
        }
        __syncthreads();
        mma_step(As, Bs, acc, ty, tx);
        __syncthreads();
    }

#pragma unroll
    for (int u = 0; u < 8; u++) {
        int mm = mBase + ty * 8 + u;
        int iloc = mm >> 2, hh = mm & 3;
        if (iloc >= L) continue;
        size_t id = (size_t)(s0 + iloc) * NH + 4 * g + hh;
        float inv = row_inv(id, L);
        size_t ob = id * HD + tx * 8;
        float4 cv0 = *(const float4*)(cc + ob);
        float4 cv1 = *(const float4*)(cc + ob + 4);
        float2 f0 = unpk(acc[u][0]), f1 = unpk(acc[u][1]);
        float2 f2 = unpk(acc[u][2]), f3 = unpk(acc[u][3]);
        *(float4*)(outc + ob)     = make_float4(cv0.x + inv * f0.x, cv0.y + inv * f0.y,
                                                cv0.z + inv * f1.x, cv0.w + inv * f1.y);
        *(float4*)(outc + ob + 4) = make_float4(cv1.x + inv * f2.x, cv1.y + inv * f2.y,
                                                cv1.z + inv * f3.x, cv1.w + inv * f3.y);
    }
}

// ---------------- K4: salient rows: out = inv * (E @ v_cache_new) ----------------
__global__ void __launch_bounds__(256) k_osal(const float* __restrict__ v, const float* __restrict__ vc,
                                              float* __restrict__ outc) {
    const int s = blockIdx.z >> 3, g = blockIdx.z & 7;
    const int s0 = g_cu[s];
    const int L = g_cu[s + 1] - s0;
    const int salst = g_salst[s], salcnt = g_salcnt[s];
    const int mBase = blockIdx.y * 128;
    if (mBase >= 4 * salcnt) return;

    __shared__ float As[32][128];
    __shared__ float Bs[32][128];
    const int t = threadIdx.x;
    const int tx = t & 15, ty = t >> 4;

    ull acc[8][4];
#pragma unroll
    for (int u = 0; u < 8; u++)
#pragma unroll
        for (int v2 = 0; v2 < 4; v2++) acc[u][v2] = 0ull;

    for (int k0 = 0; k0 < L; k0 += 32) {
#pragma unroll
        for (int it = 0; it < 4; it++) {
            int m = (t >> 3) + 32 * it;
            int j4 = (t & 7) * 4;
            int mm = mBase + m;
            int sq = mm >> 2, hh = mm & 3;
            float4 va = make_float4(0.f, 0.f, 0.f, 0.f);
            if (sq < salcnt) {
                int gi = g_idx[salst + sq];
                va = *(const float4*)(g_S + ((size_t)gi * NH + 4 * g + hh) * SMAXK + k0 + j4);
            }
            As[j4 + 0][m] = va.x; As[j4 + 1][m] = va.y; As[j4 + 2][m] = va.z; As[j4 + 3][m] = va.w;

            int j = (t >> 5) + 8 * it;
            int n4 = (t & 31) * 4;
            float4 vb = make_float4(0.f, 0.f, 0.f, 0.f);
            if (k0 + j < L) {
                int jg = s0 + k0 + j;
                int sp = g_salpos[jg];
                const float* src = (sp >= 0) ? (v + ((size_t)sp * NKV + g) * HD)
                                             : (vc + ((size_t)jg * NKV + g) * HD);
                vb = *(const float4*)(src + n4);
            }
            *(float4*)&Bs[j][n4] = vb;
        }
        __syncthreads();
        mma_step(As, Bs, acc, ty, tx);
        __syncthreads();
    }

#pragma unroll
    for (int u = 0; u < 8; u++) {
        int mm = mBase + ty * 8 + u;
        int sq = mm >> 2, hh = mm & 3;
        if (sq >= salcnt) continue;
        int gi = g_idx[salst + sq];
        size_t id = (size_t)gi * NH + 4 * g + hh;
        float inv = row_inv(id, L);
        size_t ob = id * HD + tx * 8;
        float2 f0 = unpk(acc[u][0]), f1 = unpk(acc[u][1]);
        float2 f2 = unpk(acc[u][2]), f3 = unpk(acc[u][3]);
        *(float4*)(outc + ob)     = make_float4(inv * f0.x, inv * f0.y, inv * f1.x, inv * f1.y);
        *(float4*)(outc + ob + 4) = make_float4(inv * f2.x, inv * f2.y, inv * f3.x, inv * f3.y);
    }
}

// ---------------- K5: per-row cosine similarity ----------------
__global__ void __launch_bounds__(256) k_cos(const float* __restrict__ cc, const float* __restrict__ outc,
                                             float* __restrict__ cosv) {
    __shared__ float sh[3][256];
    size_t base = (size_t)blockIdx.x * (NH * HD);
    const float4* a4 = (const float4*)(cc + base);
    const float4* b4 = (const float4*)(outc + base);
    float ab = 0.f, aa = 0.f, bb = 0.f;
    for (int j = threadIdx.x; j < (NH * HD) / 4; j += 256) {
        float4 x = a4[j], y = b4[j];
        ab += x.x * y.x + x.y * y.y + x.z * y.z + x.w * y.w;
        aa += x.x * x.x + x.y * x.y + x.z * x.z + x.w * x.w;
        bb += y.x * y.x + y.y * y.y + y.z * y.z + y.w * y.w;
    }
    sh[0][threadIdx.x] = ab; sh[1][threadIdx.x] = aa; sh[2][threadIdx.x] = bb;
    __syncthreads();
    for (int o = 128; o; o >>= 1) {
        if (threadIdx.x < o) {
            sh[0][threadIdx.x] += sh[0][threadIdx.x + o];
            sh[1][threadIdx.x] += sh[1][threadIdx.x + o];
            sh[2][threadIdx.x] += sh[2][threadIdx.x + o];
        }
        __syncthreads();
    }
    if (threadIdx.x == 0)
        cosv[blockIdx.x] = sh[0][0] / (sqrtf(sh[1][0]) * sqrtf(sh[2][0]) + 1e-8f);
}

// ---------------- launch ----------------
extern "C" void kernel_launch(void* const* d_in, const int* in_sizes, int n_in,
                              void* d_out, int out_size) {
    const float* q       = (const float*)d_in[0];
    const float* k       = (const float*)d_in[1];
    const float* v       = (const float*)d_in[2];
    const float* v_cache = (const float*)d_in[3];
    const float* c_cache = (const float*)d_in[4];
    const void*  idx     = d_in[5];
    const void*  cu      = d_in[6];

    float* outc = (float*)d_out;
    float* cosv = outc + (size_t)(out_size - TT);

    cudaFuncSetAttribute(k_qk_hmma, cudaFuncAttributeMaxDynamicSharedMemorySize, 131072);

    k_prep<<<1, 256>>>(idx, cu);
    k_vdelta<<<NSALT, 256>>>(v, v_cache);
    k_cvt<<<10240, 256>>>(q, k);
    k_qk_hmma<<<dim3(4, 16, 32), 256, 131072>>>();
    k_delta<<<dim3(1, 16, 32), 256>>>(c_cache, outc);
    k_osal<<<dim3(1, 4, 32), 256>>>(v, v_cache, outc);
    k_cos<<<TT, 256>>>(c_cache, outc, cosv);
}

// round 5
// speedup vs baseline: 1.7140x; 1.4566x over previous
#include <cuda_runtime.h>
#include <cuda_bf16.h>
#include <math.h>
#include <stdint.h>

typedef unsigned long long ull;
typedef long long ll;

#define TT    2048
#define NH    32
#define NKV   8
#define HD    128
#define NSALT 512
#define NSEG  4
#define SMAXK 512
#define SCALE_F 0.08838834764831845f

// ---------------- scratch (device globals: allocation-free) ----------------
__device__ float g_inv[(size_t)TT * NH];                       // 1/rowsum
__device__ __nv_bfloat16 g_qhi[(size_t)TT * NH * HD];
__device__ __nv_bfloat16 g_qlo[(size_t)TT * NH * HD];
__device__ __nv_bfloat16 g_khi[(size_t)TT * NKV * HD];
__device__ __nv_bfloat16 g_klo[(size_t)TT * NKV * HD];
__device__ __nv_bfloat16 g_Psal_hi[(size_t)TT * NH * 128];     // P at salient cols (all rows)
__device__ __nv_bfloat16 g_Psal_lo[(size_t)TT * NH * 128];
__device__ __nv_bfloat16 g_Posal_hi[(size_t)NSALT * NH * SMAXK]; // P full-k (salient rows)
__device__ __nv_bfloat16 g_Posal_lo[(size_t)NSALT * NH * SMAXK];
__device__ __nv_bfloat16 g_vnT_hi[(size_t)NKV * HD * TT];      // v_cache_new^T [g][d][key]
__device__ __nv_bfloat16 g_vnT_lo[(size_t)NKV * HD * TT];
__device__ __nv_bfloat16 g_vdT_hi[(size_t)NKV * HD * NSALT];   // v_delta^T [g][d][sal]
__device__ __nv_bfloat16 g_vdT_lo[(size_t)NKV * HD * NSALT];
__device__ int   g_idx[NSALT];
__device__ int   g_cu[NSEG + 1];
__device__ int   g_salpos[TT];
__device__ int   g_salst[NSEG];
__device__ int   g_salcnt[NSEG];

// ---------------- helpers ----------------
__device__ __forceinline__ uint32_t smem_to_u32(const void* p) {
    uint32_t a;
    asm("{ .reg .u64 t; cvta.to.shared.u64 t, %1; cvt.u32.u64 %0, t; }" : "=r"(a) : "l"(p));
    return a;
}

__device__ __forceinline__ void ldsm4(uint32_t* r, uint32_t addr) {
    asm volatile("ldmatrix.sync.aligned.m8n8.x4.shared.b16 {%0,%1,%2,%3}, [%4];"
        : "=r"(r[0]), "=r"(r[1]), "=r"(r[2]), "=r"(r[3]) : "r"(addr));
}

__device__ __forceinline__ void mma16816(float* c, const uint32_t* a, uint32_t b0, uint32_t b1) {
    asm volatile("mma.sync.aligned.m16n8k16.row.col.f32.bf16.bf16.f32 "
        "{%0,%1,%2,%3}, {%4,%5,%6,%7}, {%8,%9}, {%0,%1,%2,%3};"
        : "+f"(c[0]), "+f"(c[1]), "+f"(c[2]), "+f"(c[3])
        : "r"(a[0]), "r"(a[1]), "r"(a[2]), "r"(a[3]), "r"(b0), "r"(b1));
}

__device__ __forceinline__ void cpa16(uint32_t dst, const void* src, bool valid) {
    int sz = valid ? 16 : 0;
    asm volatile("cp.async.cg.shared.global [%0], [%1], 16, %2;"
        :: "r"(dst), "l"(src), "r"(sz) : "memory");
}
#define CP_COMMIT() asm volatile("cp.async.commit_group;" ::: "memory")
#define CP_WAIT(n)  asm volatile("cp.async.wait_group %0;" :: "n"(n) : "memory")

// 128x128x128 bf16 3-pass HMMA tile: A hi @aOff, A lo @aOff+32768; B hi @bOff, lo +32768.
// Rows 256B, 16B-chunk XOR swizzle (chunk' = ch ^ (row&7)). 8 warps = 2(m) x 4(n).
// Accumulates into acc (fp32). Verified layout (round 4).
__device__ __forceinline__ void hmma_tile(uint32_t sb, uint32_t aOff, uint32_t bOff,
                                          float acc[4][4][4], int wid, int lane) {
    const int wm = wid >> 2, wn = wid & 3;
    uint32_t a_ad[4], a_rx[4];
#pragma unroll
    for (int mf = 0; mf < 4; mf++) {
        int row = wm * 64 + mf * 16 + (lane & 15);
        a_ad[mf] = sb + aOff + row * 256;
        a_rx[mf] = ((uint32_t)(row & 7)) << 4;
    }
    const int achunk = (lane >> 4);
    uint32_t b_ad[2], b_rx[2];
#pragma unroll
    for (int bg = 0; bg < 2; bg++) {
        int n = wn * 32 + bg * 16 + (lane & 7) + ((lane >> 4) << 3);
        b_ad[bg] = sb + bOff + n * 256;
        b_rx[bg] = ((uint32_t)(n & 7)) << 4;
    }
    const int bchunk = (lane >> 3) & 1;

#pragma unroll
    for (int ks = 0; ks < 8; ks++) {
        uint32_t ah[4][4], al[4][4];
#pragma unroll
        for (int mf = 0; mf < 4; mf++) {
            uint32_t coff = (((uint32_t)(ks * 2 + achunk)) << 4) ^ a_rx[mf];
            ldsm4(ah[mf], a_ad[mf] + coff);
            ldsm4(al[mf], a_ad[mf] + 32768 + coff);
        }
        uint32_t bh[2][4], bl[2][4];
#pragma unroll
        for (int bg = 0; bg < 2; bg++) {
            uint32_t coff = (((uint32_t)(ks * 2 + bchunk)) << 4) ^ b_rx[bg];
            ldsm4(bh[bg], b_ad[bg] + coff);
            ldsm4(bl[bg], b_ad[bg] + 32768 + coff);
        }
#pragma unroll
        for (int mf = 0; mf < 4; mf++)
#pragma unroll
            for (int nf = 0; nf < 4; nf++) {
                int bg = nf >> 1, sel = (nf & 1) * 2;
                mma16816(acc[mf][nf], ah[mf], bh[bg][sel], bh[bg][sel + 1]);
                mma16816(acc[mf][nf], ah[mf], bl[bg][sel], bl[bg][sel + 1]);
                mma16816(acc[mf][nf], al[mf], bh[bg][sel], bh[bg][sel + 1]);
            }
    }
}

__device__ __forceinline__ void bf_split(float x, __nv_bfloat16& h, __nv_bfloat16& l) {
    h = __float2bfloat16(x);
    l = __float2bfloat16(x - __bfloat162float(h));
}

// ---------------- K0a: decode indices, segment tables ----------------
__global__ void k_prep(const void* idx_raw, const void* cu_raw) {
    const int* i32 = (const int*)idx_raw;
    const int* c32 = (const int*)cu_raw;
    const bool idx64 = (i32[1] == 0);
    const bool cu64  = (c32[1] == 0);
    const int t = threadIdx.x;

    for (int i = t; i < NSALT; i += 256)
        g_idx[i] = idx64 ? (int)((const long long*)idx_raw)[i] : i32[i];
    if (t <= NSEG)
        g_cu[t] = cu64 ? (int)((const long long*)cu_raw)[t] : c32[t];
    for (int i = t; i < TT; i += 256) g_salpos[i] = -1;
    __syncthreads();
    for (int i = t; i < NSALT; i += 256) g_salpos[g_idx[i]] = i;
    if (t == 0) {
        for (int s = 0; s < NSEG; s++) {
            int a = 0;
            while (a < NSALT && g_idx[a] < g_cu[s]) a++;
            int b = a;
            while (b < NSALT && g_idx[b] < g_cu[s + 1]) b++;
            g_salst[s] = a;
            g_salcnt[s] = b - a;
        }
    }
}

// ---------------- K0b: fp32 -> bf16 hi/lo split of Q and K ----------------
__global__ void k_cvt(const float* __restrict__ q, const float* __restrict__ kk) {
    const int nq4 = TT * NH * HD / 4;
    int i = blockIdx.x * 256 + threadIdx.x;
    float4 x;
    __nv_bfloat162 *h2, *l2;
    if (i < nq4) {
        x = ((const float4*)q)[i];
        h2 = (__nv_bfloat162*)g_qhi + 2 * (size_t)i;
        l2 = (__nv_bfloat162*)g_qlo + 2 * (size_t)i;
    } else {
        int j = i - nq4;
        x = ((const float4*)kk)[j];
        h2 = (__nv_bfloat162*)g_khi + 2 * (size_t)j;
        l2 = (__nv_bfloat162*)g_klo + 2 * (size_t)j;
    }
    __nv_bfloat162 a = __float22bfloat162_rn(make_float2(x.x, x.y));
    __nv_bfloat162 b = __float22bfloat162_rn(make_float2(x.z, x.w));
    __nv_bfloat162 al = __float22bfloat162_rn(make_float2(x.x - __low2float(a), x.y - __high2float(a)));
    __nv_bfloat162 bl = __float22bfloat162_rn(make_float2(x.z - __low2float(b), x.w - __high2float(b)));
    h2[0] = a; h2[1] = b; l2[0] = al; l2[1] = bl;
}

// ---------------- K0c: build v_cache_new^T hi/lo [g][d][key] ----------------
__global__ void k_build_vn(const float* __restrict__ v, const float* __restrict__ vc) {
    extern __shared__ float tile[];   // [128][129]
    const int kc = blockIdx.x, g = blockIdx.y;
    const int tid = threadIdx.x;
#pragma unroll 4
    for (int it = 0; it < 16; it++) {
        int fi = tid + it * 256;                 // 0..4095 float4s
        int key = fi >> 5, c4 = fi & 31;
        int gk = kc * 128 + key;
        int sp = g_salpos[gk];
        const float* src = (sp >= 0) ? v + ((size_t)sp * NKV + g) * HD + c4 * 4
                                     : vc + ((size_t)gk * NKV + g) * HD + c4 * 4;
        float4 x = *(const float4*)src;
        float* tr = tile + key * 129 + c4 * 4;
        tr[0] = x.x; tr[1] = x.y; tr[2] = x.z; tr[3] = x.w;
    }
    __syncthreads();
#pragma unroll 4
    for (int it = 0; it < 32; it++) {
        int wi = tid + it * 256;                 // 0..8191 bf16x2 words
        int d = wi >> 6, kp = wi & 63;
        float v0 = tile[(2 * kp) * 129 + d], v1 = tile[(2 * kp + 1) * 129 + d];
        __nv_bfloat16 h0, l0, h1, l1;
        bf_split(v0, h0, l0); bf_split(v1, h1, l1);
        __nv_bfloat162 ph; ph.x = h0; ph.y = h1;
        __nv_bfloat162 pl; pl.x = l0; pl.y = l1;
        size_t dst = ((size_t)g * HD + d) * TT + kc * 128 + 2 * kp;
        *(__nv_bfloat162*)(g_vnT_hi + dst) = ph;
        *(__nv_bfloat162*)(g_vnT_lo + dst) = pl;
    }
}

// ---------------- K0d: build v_delta^T hi/lo [g][d][sal] ----------------
__global__ void k_build_vd(const float* __restrict__ v, const float* __restrict__ vc) {
    extern __shared__ float tile[];   // [128][129]
    const int kc = blockIdx.x, g = blockIdx.y;
    const int tid = threadIdx.x;
#pragma unroll 4
    for (int it = 0; it < 16; it++) {
        int fi = tid + it * 256;
        int sidx = fi >> 5, c4 = fi & 31;
        int sal = kc * 128 + sidx;
        const float* pv = v  + ((size_t)sal * NKV + g) * HD + c4 * 4;
        const float* pc = vc + ((size_t)g_idx[sal] * NKV + g) * HD + c4 * 4;
        float4 a = *(const float4*)pv;
        float4 b = *(const float4*)pc;
        float* tr = tile + sidx * 129 + c4 * 4;
        tr[0] = a.x - b.x; tr[1] = a.y - b.y; tr[2] = a.z - b.z; tr[3] = a.w - b.w;
    }
    __syncthreads();
#pragma unroll 4
    for (int it = 0; it < 32; it++) {
        int wi = tid + it * 256;
        int d = wi >> 6, kp = wi & 63;
        float v0 = tile[(2 * kp) * 129 + d], v1 = tile[(2 * kp + 1) * 129 + d];
        __nv_bfloat16 h0, l0, h1, l1;
        bf_split(v0, h0, l0); bf_split(v1, h1, l1);
        __nv_bfloat162 ph; ph.x = h0; ph.y = h1;
        __nv_bfloat162 pl; pl.x = l0; pl.y = l1;
        size_t dst = ((size_t)g * HD + d) * NSALT + kc * 128 + 2 * kp;
        *(__nv_bfloat162*)(g_vdT_hi + dst) = ph;
        *(__nv_bfloat162*)(g_vdT_lo + dst) = pl;
    }
}

// ---------------- K1: persistent fused QK^T + exp + rowsum (cp.async pipelined) ----------------
__device__ __forceinline__ void qk_loadA(uint32_t sb, int tid, int mBase, int s0, int L, int g) {
#pragma unroll
    for (int it = 0; it < 8; it++) {
        int idx = tid + it * 256;
        int r = idx >> 4, ch = idx & 15;
        uint32_t d = (uint32_t)(r * 256) + (((uint32_t)(ch ^ (r & 7))) << 4);
        int mm = mBase + r, il = mm >> 2, hh = mm & 3;
        bool v = il < L;
        size_t o = v ? (((size_t)(s0 + il) * NH + 4 * g + hh) * HD + ch * 8) : 0;
        cpa16(sb + d, g_qhi + o, v);
        cpa16(sb + 32768 + d, g_qlo + o, v);
    }
}
__device__ __forceinline__ void qk_loadB(uint32_t sb, uint32_t bOff, int tid, int nt, int s0, int L, int g) {
#pragma unroll
    for (int it = 0; it < 8; it++) {
        int idx = tid + it * 256;
        int r = idx >> 4, ch = idx & 15;
        uint32_t d = (uint32_t)(r * 256) + (((uint32_t)(ch ^ (r & 7))) << 4);
        int jg = nt * 128 + r;
        bool v = jg < L;
        size_t o = v ? (((size_t)(s0 + jg) * NKV + g) * HD + ch * 8) : 0;
        cpa16(sb + bOff + d, g_khi + o, v);
        cpa16(sb + bOff + 32768 + d, g_klo + o, v);
    }
}

__global__ void __launch_bounds__(256, 1) k_qk() {
    extern __shared__ char dsm[];
    const int sg = blockIdx.y;
    const int s = sg >> 3, g = sg & 7;
    const int s0 = g_cu[s];
    const int L = g_cu[s + 1] - s0;
    const int mBase = blockIdx.x * 128;
    if (mBase >= 4 * L) return;
    const int salst = g_salst[s];

    const int tid = threadIdx.x, wid = tid >> 5, lane = tid & 31;
    const int wm = wid >> 2, wn = wid & 3;
    const uint32_t sb = smem_to_u32(dsm);

    // per-row metadata (constant across n-tiles)
    size_t id0[4], id1[4];
    ll pb0[4], pb1[4];
    bool ok0[4], ok1[4];
#pragma unroll
    for (int mf = 0; mf < 4; mf++) {
        int mr0 = mBase + wm * 64 + mf * 16 + (lane >> 2);
        int mr1 = mr0 + 8;
        int il0 = mr0 >> 2, h0 = mr0 & 3;
        int il1 = mr1 >> 2, h1 = mr1 & 3;
        ok0[mf] = il0 < L; ok1[mf] = il1 < L;
        id0[mf] = ok0[mf] ? ((size_t)(s0 + il0) * NH + 4 * g + h0) : 0;
        id1[mf] = ok1[mf] ? ((size_t)(s0 + il1) * NH + 4 * g + h1) : 0;
        int sp0 = ok0[mf] ? g_salpos[s0 + il0] : -1;
        int sp1 = ok1[mf] ? g_salpos[s0 + il1] : -1;
        pb0[mf] = sp0 >= 0 ? ((ll)sp0 * NH + 4 * g + h0) * SMAXK : -1;
        pb1[mf] = sp1 >= 0 ? ((ll)sp1 * NH + 4 * g + h1) * SMAXK : -1;
    }

    qk_loadA(sb, tid, mBase, s0, L, g);
    qk_loadB(sb, 65536, tid, 0, s0, L, g);
    CP_COMMIT();
    qk_loadB(sb, 131072, tid, 1, s0, L, g);
    CP_COMMIT();

    float rs0[4] = {0.f, 0.f, 0.f, 0.f}, rs1[4] = {0.f, 0.f, 0.f, 0.f};

    for (int nt = 0; nt < 4; nt++) {
        if (nt == 3) { CP_WAIT(0); } else { CP_WAIT(1); }
        __syncthreads();

        float acc[4][4][4];
#pragma unroll
        for (int a = 0; a < 4; a++)
#pragma unroll
            for (int b = 0; b < 4; b++)
#pragma unroll
                for (int c = 0; c < 4; c++) acc[a][b][c] = 0.f;

        hmma_tile(sb, 0, 65536 + (uint32_t)(nt & 1) * 65536, acc, wid, lane);
        __syncthreads();
        if (nt < 2) {
            qk_loadB(sb, 65536 + (uint32_t)(nt & 1) * 65536, tid, nt + 2, s0, L, g);
            CP_COMMIT();
        }

        // epilogue: exp, salient-col + salient-row bf16 hi/lo stores, rowsum accumulate
#pragma unroll
        for (int mf = 0; mf < 4; mf++) {
            float sA = 0.f, sB = 0.f;
#pragma unroll
            for (int nf = 0; nf < 4; nf++) {
                int col = nt * 128 + wn * 32 + nf * 8 + (lane & 3) * 2;
                float* c = acc[mf][nf];
                float e0 = (ok0[mf] && col     < L) ? __expf(c[0] * SCALE_F) : 0.f;
                float e1 = (ok0[mf] && col + 1 < L) ? __expf(c[1] * SCALE_F) : 0.f;
                float e2 = (ok1[mf] && col     < L) ? __expf(c[2] * SCALE_F) : 0.f;
                float e3 = (ok1[mf] && col + 1 < L) ? __expf(c[3] * SCALE_F) : 0.f;
                sA += e0 + e1; sB += e2 + e3;

                int spa = (col < L) ? g_salpos[s0 + col] : -1;
                int spb = (col + 1 < L) ? g_salpos[s0 + col + 1] : -1;
                if (spa >= 0) {
                    int sc = spa - salst;
                    if (ok0[mf]) { __nv_bfloat16 h, l; bf_split(e0, h, l);
                        g_Psal_hi[id0[mf] * 128 + sc] = h; g_Psal_lo[id0[mf] * 128 + sc] = l; }
                    if (ok1[mf]) { __nv_bfloat16 h, l; bf_split(e2, h, l);
                        g_Psal_hi[id1[mf] * 128 + sc] = h; g_Psal_lo[id1[mf] * 128 + sc] = l; }
                }
                if (spb >= 0) {
                    int sc = spb - salst;
                    if (ok0[mf]) { __nv_bfloat16 h, l; bf_split(e1, h, l);
                        g_Psal_hi[id0[mf] * 128 + sc] = h; g_Psal_lo[id0[mf] * 128 + sc] = l; }
                    if (ok1[mf]) { __nv_bfloat16 h, l; bf_split(e3, h, l);
                        g_Psal_hi[id1[mf] * 128 + sc] = h; g_Psal_lo[id1[mf] * 128 + sc] = l; }
                }
                if (pb0[mf] >= 0 && col < L) {
                    __nv_bfloat16 h0, l0, h1, l1;
                    bf_split(e0, h0, l0); bf_split(e1, h1, l1);
                    __nv_bfloat162 ph; ph.x = h0; ph.y = h1;
                    __nv_bfloat162 pl; pl.x = l0; pl.y = l1;
                    *(__nv_bfloat162*)(g_Posal_hi + pb0[mf] + col) = ph;
                    *(__nv_bfloat162*)(g_Posal_lo + pb0[mf] + col) = pl;
                }
                if (pb1[mf] >= 0 && col < L) {
                    __nv_bfloat16 h0, l0, h1, l1;
                    bf_split(e2, h0, l0); bf_split(e3, h1, l1);
                    __nv_bfloat162 ph; ph.x = h0; ph.y = h1;
                    __nv_bfloat162 pl; pl.x = l0; pl.y = l1;
                    *(__nv_bfloat162*)(g_Posal_hi + pb1[mf] + col) = ph;
                    *(__nv_bfloat162*)(g_Posal_lo + pb1[mf] + col) = pl;
                }
            }
            rs0[mf] += sA; rs1[mf] += sB;
        }
    }

    // final rowsum reduction -> g_inv
#pragma unroll
    for (int mf = 0; mf < 4; mf++) {
        rs0[mf] += __shfl_xor_sync(0xffffffffu, rs0[mf], 1);
        rs0[mf] += __shfl_xor_sync(0xffffffffu, rs0[mf], 2);
        rs1[mf] += __shfl_xor_sync(0xffffffffu, rs1[mf], 1);
        rs1[mf] += __shfl_xor_sync(0xffffffffu, rs1[mf], 2);
    }
    __syncthreads();
    float* red = (float*)(dsm + 65536);
    if ((lane & 3) == 0) {
#pragma unroll
        for (int mf = 0; mf < 4; mf++) {
            int r0 = wm * 64 + mf * 16 + (lane >> 2);
            red[r0 * 4 + wn] = rs0[mf];
            red[(r0 + 8) * 4 + wn] = rs1[mf];
        }
    }
    __syncthreads();
    if (tid < 128) {
        int mm = mBase + tid, il = mm >> 2, h = mm & 3;
        if (il < L) {
            float s4 = red[tid * 4] + red[tid * 4 + 1] + red[tid * 4 + 2] + red[tid * 4 + 3];
            g_inv[(size_t)(s0 + il) * NH + 4 * g + h] = 1.f / s4;
        }
    }
}

// ---------------- K2: out = c_cache + inv * (Psal @ vdelta^T)  (HMMA) ----------------
__global__ void __launch_bounds__(256, 1) k_delta(const float* __restrict__ cc, float* __restrict__ outc) {
    extern __shared__ char dsm[];
    const int sg = blockIdx.y;
    const int s = sg >> 3, g = sg & 7;
    const int s0 = g_cu[s];
    const int L = g_cu[s + 1] - s0;
    const int salst = g_salst[s], salcnt = g_salcnt[s];
    const int mBase = blockIdx.x * 128;
    if (mBase >= 4 * L) return;

    const int tid = threadIdx.x, wid = tid >> 5, lane = tid & 31;
    const int wm = wid >> 2, wn = wid & 3;
    const uint32_t sb = smem_to_u32(dsm);
    const uint4 z4 = make_uint4(0, 0, 0, 0);

#pragma unroll
    for (int it = 0; it < 8; it++) {
        int idx = tid + it * 256;
        int r = idx >> 4, ch = idx & 15;
        uint32_t d = (uint32_t)(r * 256) + (((uint32_t)(ch ^ (r & 7))) << 4);
        int mm = mBase + r, il = mm >> 2, hh = mm & 3;
        bool va = (il < L) && (ch * 8 < salcnt);
        size_t ia = ((size_t)(s0 + il) * NH + 4 * g + hh) * 128 + ch * 8;
        *(uint4*)(dsm + d)         = va ? *(const uint4*)(g_Psal_hi + ia) : z4;
        *(uint4*)(dsm + 32768 + d) = va ? *(const uint4*)(g_Psal_lo + ia) : z4;
        bool vb = (ch * 8 < salcnt);
        size_t ib = ((size_t)(g * HD + r)) * NSALT + salst + ch * 8;
        *(uint4*)(dsm + 65536 + d) = vb ? *(const uint4*)(g_vdT_hi + ib) : z4;
        *(uint4*)(dsm + 98304 + d) = vb ? *(const uint4*)(g_vdT_lo + ib) : z4;
    }
    __syncthreads();

    float acc[4][4][4];
#pragma unroll
    for (int a = 0; a < 4; a++)
#pragma unroll
        for (int b = 0; b < 4; b++)
#pragma unroll
            for (int c = 0; c < 4; c++) acc[a][b][c] = 0.f;
    hmma_tile(sb, 0, 65536, acc, wid, lane);

#pragma unroll
    for (int mf = 0; mf < 4; mf++) {
        int mr0 = mBase + wm * 64 + mf * 16 + (lane >> 2);
        int mr1 = mr0 + 8;
        int il0 = mr0 >> 2, h0 = mr0 & 3;
        int il1 = mr1 >> 2, h1 = mr1 & 3;
        bool ok0 = il0 < L, ok1 = il1 < L;
        size_t id0 = (size_t)(s0 + il0) * NH + 4 * g + h0;
        size_t id1 = (size_t)(s0 + il1) * NH + 4 * g + h1;
        float inv0 = ok0 ? g_inv[id0] : 0.f;
        float inv1 = ok1 ? g_inv[id1] : 0.f;
#pragma unroll
        for (int nf = 0; nf < 4; nf++) {
            int dcol = wn * 32 + nf * 8 + (lane & 3) * 2;
            float* c = acc[mf][nf];
            if (ok0) {
                size_t ob = id0 * HD + dcol;
                float2 cv = *(const float2*)(cc + ob);
                *(float2*)(outc + ob) = make_float2(cv.x + inv0 * c[0], cv.y + inv0 * c[1]);
            }
            if (ok1) {
                size_t ob = id1 * HD + dcol;
                float2 cv = *(const float2*)(cc + ob);
                *(float2*)(outc + ob) = make_float2(cv.x + inv1 * c[2], cv.y + inv1 * c[3]);
            }
        }
    }
}

// ---------------- K3: salient rows: out = inv * (P @ vnew^T)  (HMMA, overwrite) ----------------
__global__ void __launch_bounds__(256, 1) k_osal(float* __restrict__ outc) {
    extern __shared__ char dsm[];
    const int sg = blockIdx.y;
    const int s = sg >> 3, g = sg & 7;
    const int s0 = g_cu[s];
    const int L = g_cu[s + 1] - s0;
    const int salst = g_salst[s], salcnt = g_salcnt[s];
    const int mBase = blockIdx.x * 128;
    if (mBase >= 4 * salcnt) return;

    const int tid = threadIdx.x, wid = tid >> 5, lane = tid & 31;
    const int wm = wid >> 2, wn = wid & 3;
    const uint32_t sb = smem_to_u32(dsm);
    const uint4 z4 = make_uint4(0, 0, 0, 0);

    float acc[4][4][4];
#pragma unroll
    for (int a = 0; a < 4; a++)
#pragma unroll
        for (int b = 0; b < 4; b++)
#pragma unroll
            for (int c = 0; c < 4; c++) acc[a][b][c] = 0.f;

    for (int kc = 0; kc * 128 < L; kc++) {
#pragma unroll
        for (int it = 0; it < 8; it++) {
            int idx = tid + it * 256;
            int r = idx >> 4, ch = idx & 15;
            uint32_t d = (uint32_t)(r * 256) + (((uint32_t)(ch ^ (r & 7))) << 4);
            int m = mBase + r, saloc = m >> 2, hh = m & 3;
            int kk = kc * 128 + ch * 8;
            bool va = (saloc < salcnt) && (kk < L);
            size_t ia = ((size_t)(salst + saloc) * NH + 4 * g + hh) * SMAXK + kk;
            *(uint4*)(dsm + d)         = va ? *(const uint4*)(g_Posal_hi + ia) : z4;
            *(uint4*)(dsm + 32768 + d) = va ? *(const uint4*)(g_Posal_lo + ia) : z4;
            bool vb = (kk < L);
            size_t ib = ((size_t)(g * HD + r)) * TT + s0 + kk;
            *(uint4*)(dsm + 65536 + d) = vb ? *(const uint4*)(g_vnT_hi + ib) : z4;
            *(uint4*)(dsm + 98304 + d) = vb ? *(const uint4*)(g_vnT_lo + ib) : z4;
        }
        __syncthreads();
        hmma_tile(sb, 0, 65536, acc, wid, lane);
        __syncthreads();
    }

#pragma unroll
    for (int mf = 0; mf < 4; mf++) {
        int mr0 = mBase + wm * 64 + mf * 16 + (lane >> 2);
        int mr1 = mr0 + 8;
        int sa0 = mr0 >> 2, h0 = mr0 & 3;
        int sa1 = mr1 >> 2, h1 = mr1 & 3;
        bool ok0 = sa0 < salcnt, ok1 = sa1 < salcnt;
        size_t id0 = 0, id1 = 0;
        float inv0 = 0.f, inv1 = 0.f;
        if (ok0) { id0 = (size_t)g_idx[salst + sa0] * NH + 4 * g + h0; inv0 = g_inv[id0]; }
        if (ok1) { id1 = (size_t)g_idx[salst + sa1] * NH + 4 * g + h1; inv1 = g_inv[id1]; }
#pragma unroll
        for (int nf = 0; nf < 4; nf++) {
            int dcol = wn * 32 + nf * 8 + (lane & 3) * 2;
            float* c = acc[mf][nf];
            if (ok0) *(float2*)(outc + id0 * HD + dcol) = make_float2(inv0 * c[0], inv0 * c[1]);
            if (ok1) *(float2*)(outc + id1 * HD + dcol) = make_float2(inv1 * c[2], inv1 * c[3]);
        }
    }
}

// ---------------- K4: per-row cosine similarity ----------------
__global__ void __launch_bounds__(256) k_cos(const float* __restrict__ cc, const float* __restrict__ outc,
                                             float* __restrict__ cosv) {
    __shared__ float sh[3][256];
    size_t base = (size_t)blockIdx.x * (NH * HD);
    const float4* a4 = (const float4*)(cc + base);
    const float4* b4 = (const float4*)(outc + base);
    float ab = 0.f, aa = 0.f, bb = 0.f;
    for (int j = threadIdx.x; j < (NH * HD) / 4; j += 256) {
        float4 x = a4[j], y = b4[j];
        ab += x.x * y.x + x.y * y.y + x.z * y.z + x.w * y.w;
        aa += x.x * x.x + x.y * x.y + x.z * x.z + x.w * x.w;
        bb += y.x * y.x + y.y * y.y + y.z * y.z + y.w * y.w;
    }
    sh[0][threadIdx.x] = ab; sh[1][threadIdx.x] = aa; sh[2][threadIdx.x] = bb;
    __syncthreads();
    for (int o = 128; o; o >>= 1) {
        if (threadIdx.x < o) {
            sh[0][threadIdx.x] += sh[0][threadIdx.x + o];
            sh[1][threadIdx.x] += sh[1][threadIdx.x + o];
            sh[2][threadIdx.x] += sh[2][threadIdx.x + o];
        }
        __syncthreads();
    }
    if (threadIdx.x == 0)
        cosv[blockIdx.x] = sh[0][0] / (sqrtf(sh[1][0]) * sqrtf(sh[2][0]) + 1e-8f);
}

// ---------------- launch ----------------
extern "C" void kernel_launch(void* const* d_in, const int* in_sizes, int n_in,
                              void* d_out, int out_size) {
    const float* q       = (const float*)d_in[0];
    const float* k       = (const float*)d_in[1];
    const float* v       = (const float*)d_in[2];
    const float* v_cache = (const float*)d_in[3];
    const float* c_cache = (const float*)d_in[4];
    const void*  idx     = d_in[5];
    const void*  cu      = d_in[6];

    float* outc = (float*)d_out;
    float* cosv = outc + (size_t)(out_size - TT);

    cudaFuncSetAttribute(k_qk,       cudaFuncAttributeMaxDynamicSharedMemorySize, 196608);
    cudaFuncSetAttribute(k_delta,    cudaFuncAttributeMaxDynamicSharedMemorySize, 131072);
    cudaFuncSetAttribute(k_osal,     cudaFuncAttributeMaxDynamicSharedMemorySize, 131072);
    cudaFuncSetAttribute(k_build_vn, cudaFuncAttributeMaxDynamicSharedMemorySize, 66048);
    cudaFuncSetAttribute(k_build_vd, cudaFuncAttributeMaxDynamicSharedMemorySize, 66048);

    k_prep<<<1, 256>>>(idx, cu);
    k_cvt<<<10240, 256>>>(q, k);
    k_build_vn<<<dim3(16, 8), 256, 66048>>>(v, v_cache);
    k_build_vd<<<dim3(4, 8), 256, 66048>>>(v, v_cache);
    k_qk<<<dim3(16, 32), 256, 196608>>>();
    k_delta<<<dim3(16, 32), 256, 131072>>>(c_cache, outc);
    k_osal<<<dim3(4, 32), 256, 131072>>>(outc);
    k_cos<<<TT, 256>>>(c_cache, outc, cosv);
}

// round 6
// speedup vs baseline: 1.9056x; 1.1118x over previous
#include <cuda_runtime.h>
#include <cuda_bf16.h>
#include <math.h>
#include <stdint.h>

typedef unsigned long long ull;
typedef long long ll;

#define TT    2048
#define NH    32
#define NKV   8
#define HD    128
#define NSALT 512
#define NSEG  4
#define SMAXK 512
#define SCALE_F 0.08838834764831845f

#define CVT_BLKS 10240
#define VN_BLKS  512   // 64 key-tiles x 8 groups (32 keys each)
#define VD_BLKS  128   // 16 sal-tiles x 8 groups

// ---------------- scratch (device globals: allocation-free) ----------------
__device__ float g_inv[(size_t)TT * NH];                       // 1/rowsum
__device__ __nv_bfloat16 g_qhi[(size_t)TT * NH * HD];
__device__ __nv_bfloat16 g_qlo[(size_t)TT * NH * HD];
__device__ __nv_bfloat16 g_khi[(size_t)TT * NKV * HD];
__device__ __nv_bfloat16 g_klo[(size_t)TT * NKV * HD];
__device__ __nv_bfloat16 g_Psal_hi[(size_t)TT * NH * 128];     // P at salient cols (all rows)
__device__ __nv_bfloat16 g_Psal_lo[(size_t)TT * NH * 128];
__device__ __nv_bfloat16 g_Posal_hi[(size_t)NSALT * NH * SMAXK]; // P full-k (salient rows)
__device__ __nv_bfloat16 g_Posal_lo[(size_t)NSALT * NH * SMAXK];
__device__ __nv_bfloat16 g_vnT_hi[(size_t)NKV * HD * TT];      // v_cache_new^T [g][d][key]
__device__ __nv_bfloat16 g_vnT_lo[(size_t)NKV * HD * TT];
__device__ __nv_bfloat16 g_vdT_hi[(size_t)NKV * HD * NSALT];   // v_delta^T [g][d][sal]
__device__ __nv_bfloat16 g_vdT_lo[(size_t)NKV * HD * NSALT];
__device__ int   g_idx[NSALT];
__device__ int   g_cu[NSEG + 1];
__device__ int   g_salpos[TT];
__device__ int   g_salst[NSEG];
__device__ int   g_salcnt[NSEG];

// ---------------- helpers ----------------
__device__ __forceinline__ uint32_t smem_to_u32(const void* p) {
    uint32_t a;
    asm("{ .reg .u64 t; cvta.to.shared.u64 t, %1; cvt.u32.u64 %0, t; }" : "=r"(a) : "l"(p));
    return a;
}

__device__ __forceinline__ void ldsm4(uint32_t* r, uint32_t addr) {
    asm volatile("ldmatrix.sync.aligned.m8n8.x4.shared.b16 {%0,%1,%2,%3}, [%4];"
        : "=r"(r[0]), "=r"(r[1]), "=r"(r[2]), "=r"(r[3]) : "r"(addr));
}

__device__ __forceinline__ void mma16816(float* c, const uint32_t* a, uint32_t b0, uint32_t b1) {
    asm volatile("mma.sync.aligned.m16n8k16.row.col.f32.bf16.bf16.f32 "
        "{%0,%1,%2,%3}, {%4,%5,%6,%7}, {%8,%9}, {%0,%1,%2,%3};"
        : "+f"(c[0]), "+f"(c[1]), "+f"(c[2]), "+f"(c[3])
        : "r"(a[0]), "r"(a[1]), "r"(a[2]), "r"(a[3]), "r"(b0), "r"(b1));
}

__device__ __forceinline__ void cpa16(uint32_t dst, const void* src, bool valid) {
    int sz = valid ? 16 : 0;
    asm volatile("cp.async.cg.shared.global [%0], [%1], 16, %2;"
        :: "r"(dst), "l"(src), "r"(sz) : "memory");
}
#define CP_COMMIT() asm volatile("cp.async.commit_group;" ::: "memory")
#define CP_WAIT(n)  asm volatile("cp.async.wait_group %0;" :: "n"(n) : "memory")

// 128x128x128 bf16 3-pass HMMA tile (verified round 4). Rows 256B, 16B-chunk XOR swizzle.
__device__ __forceinline__ void hmma_tile(uint32_t sb, uint32_t aOff, uint32_t bOff,
                                          float acc[4][4][4], int wid, int lane) {
    const int wm = wid >> 2, wn = wid & 3;
    uint32_t a_ad[4], a_rx[4];
#pragma unroll
    for (int mf = 0; mf < 4; mf++) {
        int row = wm * 64 + mf * 16 + (lane & 15);
        a_ad[mf] = sb + aOff + row * 256;
        a_rx[mf] = ((uint32_t)(row & 7)) << 4;
    }
    const int achunk = (lane >> 4);
    uint32_t b_ad[2], b_rx[2];
#pragma unroll
    for (int bg = 0; bg < 2; bg++) {
        int n = wn * 32 + bg * 16 + (lane & 7) + ((lane >> 4) << 3);
        b_ad[bg] = sb + bOff + n * 256;
        b_rx[bg] = ((uint32_t)(n & 7)) << 4;
    }
    const int bchunk = (lane >> 3) & 1;

#pragma unroll
    for (int ks = 0; ks < 8; ks++) {
        uint32_t ah[4][4], al[4][4];
#pragma unroll
        for (int mf = 0; mf < 4; mf++) {
            uint32_t coff = (((uint32_t)(ks * 2 + achunk)) << 4) ^ a_rx[mf];
            ldsm4(ah[mf], a_ad[mf] + coff);
            ldsm4(al[mf], a_ad[mf] + 32768 + coff);
        }
        uint32_t bh[2][4], bl[2][4];
#pragma unroll
        for (int bg = 0; bg < 2; bg++) {
            uint32_t coff = (((uint32_t)(ks * 2 + bchunk)) << 4) ^ b_rx[bg];
            ldsm4(bh[bg], b_ad[bg] + coff);
            ldsm4(bl[bg], b_ad[bg] + 32768 + coff);
        }
#pragma unroll
        for (int mf = 0; mf < 4; mf++)
#pragma unroll
            for (int nf = 0; nf < 4; nf++) {
                int bg = nf >> 1, sel = (nf & 1) * 2;
                mma16816(acc[mf][nf], ah[mf], bh[bg][sel], bh[bg][sel + 1]);
                mma16816(acc[mf][nf], ah[mf], bl[bg][sel], bl[bg][sel + 1]);
                mma16816(acc[mf][nf], al[mf], bh[bg][sel], bh[bg][sel + 1]);
            }
    }
}

__device__ __forceinline__ void bf_split(float x, __nv_bfloat16& h, __nv_bfloat16& l) {
    h = __float2bfloat16(x);
    l = __float2bfloat16(x - __bfloat162float(h));
}

// ---------------- K0a: decode indices, segment tables ----------------
__global__ void k_prep(const void* idx_raw, const void* cu_raw) {
    const int* i32 = (const int*)idx_raw;
    const int* c32 = (const int*)cu_raw;
    const bool idx64 = (i32[1] == 0);
    const bool cu64  = (c32[1] == 0);
    const int t = threadIdx.x;

    for (int i = t; i < NSALT; i += 256)
        g_idx[i] = idx64 ? (int)((const long long*)idx_raw)[i] : i32[i];
    if (t <= NSEG)
        g_cu[t] = cu64 ? (int)((const long long*)cu_raw)[t] : c32[t];
    for (int i = t; i < TT; i += 256) g_salpos[i] = -1;
    __syncthreads();
    for (int i = t; i < NSALT; i += 256) g_salpos[g_idx[i]] = i;
    if (t == 0) {
        for (int s = 0; s < NSEG; s++) {
            int a = 0;
            while (a < NSALT && g_idx[a] < g_cu[s]) a++;
            int b = a;
            while (b < NSALT && g_idx[b] < g_cu[s + 1]) b++;
            g_salst[s] = a;
            g_salcnt[s] = b - a;
        }
    }
}

// ---------------- K0b (merged): cvt || build_vn || build_vd ----------------
__global__ void __launch_bounds__(256) k_pre(const float* __restrict__ q, const float* __restrict__ kk,
                                             const float* __restrict__ v, const float* __restrict__ vc) {
    extern __shared__ float tile[];   // [32][129] for the build branches
    const int bx = blockIdx.x;
    const int tid = threadIdx.x;

    if (bx < CVT_BLKS) {
        // ---- fp32 -> bf16 hi/lo split of Q and K
        const int nq4 = TT * NH * HD / 4;
        int i = bx * 256 + tid;
        float4 x;
        __nv_bfloat162 *h2, *l2;
        if (i < nq4) {
            x = ((const float4*)q)[i];
            h2 = (__nv_bfloat162*)g_qhi + 2 * (size_t)i;
            l2 = (__nv_bfloat162*)g_qlo + 2 * (size_t)i;
        } else {
            int j = i - nq4;
            x = ((const float4*)kk)[j];
            h2 = (__nv_bfloat162*)g_khi + 2 * (size_t)j;
            l2 = (__nv_bfloat162*)g_klo + 2 * (size_t)j;
        }
        __nv_bfloat162 a = __float22bfloat162_rn(make_float2(x.x, x.y));
        __nv_bfloat162 b = __float22bfloat162_rn(make_float2(x.z, x.w));
        __nv_bfloat162 al = __float22bfloat162_rn(make_float2(x.x - __low2float(a), x.y - __high2float(a)));
        __nv_bfloat162 bl = __float22bfloat162_rn(make_float2(x.z - __low2float(b), x.w - __high2float(b)));
        h2[0] = a; h2[1] = b; l2[0] = al; l2[1] = bl;
        return;
    }

    if (bx < CVT_BLKS + VN_BLKS) {
        // ---- build v_cache_new^T hi/lo [g][d][key], 32 keys per CTA
        int t2 = bx - CVT_BLKS;
        int kc = t2 >> 3, g = t2 & 7;     // kc in [0,64)
#pragma unroll
        for (int it = 0; it < 4; it++) {
            int fi = tid + it * 256;       // 0..1023: 32 keys x 32 float4
            int key = fi >> 5, c4 = fi & 31;
            int gk = kc * 32 + key;
            int sp = g_salpos[gk];
            const float* src = (sp >= 0) ? v + ((size_t)sp * NKV + g) * HD + c4 * 4
                                         : vc + ((size_t)gk * NKV + g) * HD + c4 * 4;
            float4 x = *(const float4*)src;
            float* tr = tile + key * 129 + c4 * 4;
            tr[0] = x.x; tr[1] = x.y; tr[2] = x.z; tr[3] = x.w;
        }
        __syncthreads();
#pragma unroll
        for (int it = 0; it < 8; it++) {
            int wi = tid + it * 256;       // 0..2047: d(128) x 16 key-pairs
            int d = wi >> 4, kp = wi & 15;
            float v0 = tile[(2 * kp) * 129 + d], v1 = tile[(2 * kp + 1) * 129 + d];
            __nv_bfloat16 h0, l0, h1, l1;
            bf_split(v0, h0, l0); bf_split(v1, h1, l1);
            __nv_bfloat162 ph; ph.x = h0; ph.y = h1;
            __nv_bfloat162 pl; pl.x = l0; pl.y = l1;
            size_t dst = ((size_t)g * HD + d) * TT + kc * 32 + 2 * kp;
            *(__nv_bfloat162*)(g_vnT_hi + dst) = ph;
            *(__nv_bfloat162*)(g_vnT_lo + dst) = pl;
        }
        return;
    }

    // ---- build v_delta^T hi/lo [g][d][sal], 32 salient per CTA
    {
        int t2 = bx - CVT_BLKS - VN_BLKS;
        int kc = t2 >> 3, g = t2 & 7;     // kc in [0,16)
#pragma unroll
        for (int it = 0; it < 4; it++) {
            int fi = tid + it * 256;
            int sidx = fi >> 5, c4 = fi & 31;
            int sal = kc * 32 + sidx;
            const float* pv = v  + ((size_t)sal * NKV + g) * HD + c4 * 4;
            const float* pc = vc + ((size_t)g_idx[sal] * NKV + g) * HD + c4 * 4;
            float4 a = *(const float4*)pv;
            float4 b = *(const float4*)pc;
            float* tr = tile + sidx * 129 + c4 * 4;
            tr[0] = a.x - b.x; tr[1] = a.y - b.y; tr[2] = a.z - b.z; tr[3] = a.w - b.w;
        }
        __syncthreads();
#pragma unroll
        for (int it = 0; it < 8; it++) {
            int wi = tid + it * 256;
            int d = wi >> 4, kp = wi & 15;
            float v0 = tile[(2 * kp) * 129 + d], v1 = tile[(2 * kp + 1) * 129 + d];
            __nv_bfloat16 h0, l0, h1, l1;
            bf_split(v0, h0, l0); bf_split(v1, h1, l1);
            __nv_bfloat162 ph; ph.x = h0; ph.y = h1;
            __nv_bfloat162 pl; pl.x = l0; pl.y = l1;
            size_t dst = ((size_t)g * HD + d) * NSALT + kc * 32 + 2 * kp;
            *(__nv_bfloat162*)(g_vdT_hi + dst) = ph;
            *(__nv_bfloat162*)(g_vdT_lo + dst) = pl;
        }
    }
}

// ---------------- K1: persistent fused QK^T + exp + rowsum (cp.async pipelined) ----------------
__device__ __forceinline__ void qk_loadA(uint32_t sb, int tid, int mBase, int s0, int L, int g) {
#pragma unroll
    for (int it = 0; it < 8; it++) {
        int idx = tid + it * 256;
        int r = idx >> 4, ch = idx & 15;
        uint32_t d = (uint32_t)(r * 256) + (((uint32_t)(ch ^ (r & 7))) << 4);
        int mm = mBase + r, il = mm >> 2, hh = mm & 3;
        bool v = il < L;
        size_t o = v ? (((size_t)(s0 + il) * NH + 4 * g + hh) * HD + ch * 8) : 0;
        cpa16(sb + d, g_qhi + o, v);
        cpa16(sb + 32768 + d, g_qlo + o, v);
    }
}
__device__ __forceinline__ void qk_loadB(uint32_t sb, uint32_t bOff, int tid, int nt, int s0, int L, int g) {
#pragma unroll
    for (int it = 0; it < 8; it++) {
        int idx = tid + it * 256;
        int r = idx >> 4, ch = idx & 15;
        uint32_t d = (uint32_t)(r * 256) + (((uint32_t)(ch ^ (r & 7))) << 4);
        int jg = nt * 128 + r;
        bool v = jg < L;
        size_t o = v ? (((size_t)(s0 + jg) * NKV + g) * HD + ch * 8) : 0;
        cpa16(sb + bOff + d, g_khi + o, v);
        cpa16(sb + bOff + 32768 + d, g_klo + o, v);
    }
}

__global__ void __launch_bounds__(256, 1) k_qk() {
    extern __shared__ char dsm[];
    __shared__ int s_sp[SMAXK];        // local salient col (sp - salst) or -1
    const int sg = blockIdx.y;
    const int s = sg >> 3, g = sg & 7;
    const int s0 = g_cu[s];
    const int L = g_cu[s + 1] - s0;
    const int mBase = blockIdx.x * 128;
    if (mBase >= 4 * L) return;
    const int salst = g_salst[s];

    const int tid = threadIdx.x, wid = tid >> 5, lane = tid & 31;
    const int wm = wid >> 2, wn = wid & 3;
    const uint32_t sb = smem_to_u32(dsm);

    for (int j = tid; j < L; j += 256) {
        int sp = g_salpos[s0 + j];
        s_sp[j] = sp >= 0 ? sp - salst : -1;
    }

    // per-row metadata (constant across n-tiles)
    size_t id0[4], id1[4];
    ll pb0[4], pb1[4];
    bool ok0[4], ok1[4];
#pragma unroll
    for (int mf = 0; mf < 4; mf++) {
        int mr0 = mBase + wm * 64 + mf * 16 + (lane >> 2);
        int mr1 = mr0 + 8;
        int il0 = mr0 >> 2, h0 = mr0 & 3;
        int il1 = mr1 >> 2, h1 = mr1 & 3;
        ok0[mf] = il0 < L; ok1[mf] = il1 < L;
        id0[mf] = ok0[mf] ? ((size_t)(s0 + il0) * NH + 4 * g + h0) : 0;
        id1[mf] = ok1[mf] ? ((size_t)(s0 + il1) * NH + 4 * g + h1) : 0;
        int sp0 = ok0[mf] ? g_salpos[s0 + il0] : -1;
        int sp1 = ok1[mf] ? g_salpos[s0 + il1] : -1;
        pb0[mf] = sp0 >= 0 ? ((ll)sp0 * NH + 4 * g + h0) * SMAXK : -1;
        pb1[mf] = sp1 >= 0 ? ((ll)sp1 * NH + 4 * g + h1) * SMAXK : -1;
    }

    qk_loadA(sb, tid, mBase, s0, L, g);
    qk_loadB(sb, 65536, tid, 0, s0, L, g);
    CP_COMMIT();
    qk_loadB(sb, 131072, tid, 1, s0, L, g);
    CP_COMMIT();

    float rs0[4] = {0.f, 0.f, 0.f, 0.f}, rs1[4] = {0.f, 0.f, 0.f, 0.f};

    for (int nt = 0; nt < 4; nt++) {
        if (nt == 3) { CP_WAIT(0); } else { CP_WAIT(1); }
        __syncthreads();

        float acc[4][4][4];
#pragma unroll
        for (int a = 0; a < 4; a++)
#pragma unroll
            for (int b = 0; b < 4; b++)
#pragma unroll
                for (int c = 0; c < 4; c++) acc[a][b][c] = 0.f;

        hmma_tile(sb, 0, 65536 + (uint32_t)(nt & 1) * 65536, acc, wid, lane);
        __syncthreads();
        if (nt < 2) {
            qk_loadB(sb, 65536 + (uint32_t)(nt & 1) * 65536, tid, nt + 2, s0, L, g);
            CP_COMMIT();
        }

        // epilogue (nf outer: one salient-column lookup per column pair)
#pragma unroll
        for (int nf = 0; nf < 4; nf++) {
            int col = nt * 128 + wn * 32 + nf * 8 + (lane & 3) * 2;
            bool c0 = col < L, c1 = col + 1 < L;
            int spa = c0 ? s_sp[col] : -1;
            int spb = c1 ? s_sp[col + 1] : -1;
#pragma unroll
            for (int mf = 0; mf < 4; mf++) {
                float* c = acc[mf][nf];
                float e0 = (ok0[mf] && c0) ? __expf(c[0] * SCALE_F) : 0.f;
                float e1 = (ok0[mf] && c1) ? __expf(c[1] * SCALE_F) : 0.f;
                float e2 = (ok1[mf] && c0) ? __expf(c[2] * SCALE_F) : 0.f;
                float e3 = (ok1[mf] && c1) ? __expf(c[3] * SCALE_F) : 0.f;
                rs0[mf] += e0 + e1;
                rs1[mf] += e2 + e3;

                if (spa >= 0) {
                    if (ok0[mf]) { __nv_bfloat16 h, l; bf_split(e0, h, l);
                        g_Psal_hi[id0[mf] * 128 + spa] = h; g_Psal_lo[id0[mf] * 128 + spa] = l; }
                    if (ok1[mf]) { __nv_bfloat16 h, l; bf_split(e2, h, l);
                        g_Psal_hi[id1[mf] * 128 + spa] = h; g_Psal_lo[id1[mf] * 128 + spa] = l; }
                }
                if (spb >= 0) {
                    if (ok0[mf]) { __nv_bfloat16 h, l; bf_split(e1, h, l);
                        g_Psal_hi[id0[mf] * 128 + spb] = h; g_Psal_lo[id0[mf] * 128 + spb] = l; }
                    if (ok1[mf]) { __nv_bfloat16 h, l; bf_split(e3, h, l);
                        g_Psal_hi[id1[mf] * 128 + spb] = h; g_Psal_lo[id1[mf] * 128 + spb] = l; }
                }
                if (pb0[mf] >= 0 && c0) {
                    __nv_bfloat16 h0, l0, h1, l1;
                    bf_split(e0, h0, l0); bf_split(e1, h1, l1);
                    __nv_bfloat162 ph; ph.x = h0; ph.y = h1;
                    __nv_bfloat162 pl; pl.x = l0; pl.y = l1;
                    *(__nv_bfloat162*)(g_Posal_hi + pb0[mf] + col) = ph;
                    *(__nv_bfloat162*)(g_Posal_lo + pb0[mf] + col) = pl;
                }
                if (pb1[mf] >= 0 && c0) {
                    __nv_bfloat16 h0, l0, h1, l1;
                    bf_split(e2, h0, l0); bf_split(e3, h1, l1);
                    __nv_bfloat162 ph; ph.x = h0; ph.y = h1;
                    __nv_bfloat162 pl; pl.x = l0; pl.y = l1;
                    *(__nv_bfloat162*)(g_Posal_hi + pb1[mf] + col) = ph;
                    *(__nv_bfloat162*)(g_Posal_lo + pb1[mf] + col) = pl;
                }
            }
        }
    }

    // final rowsum reduction -> g_inv
#pragma unroll
    for (int mf = 0; mf < 4; mf++) {
        rs0[mf] += __shfl_xor_sync(0xffffffffu, rs0[mf], 1);
        rs0[mf] += __shfl_xor_sync(0xffffffffu, rs0[mf], 2);
        rs1[mf] += __shfl_xor_sync(0xffffffffu, rs1[mf], 1);
        rs1[mf] += __shfl_xor_sync(0xffffffffu, rs1[mf], 2);
    }
    __syncthreads();
    float* red = (float*)(dsm + 65536);
    if ((lane & 3) == 0) {
#pragma unroll
        for (int mf = 0; mf < 4; mf++) {
            int r0 = wm * 64 + mf * 16 + (lane >> 2);
            red[r0 * 4 + wn] = rs0[mf];
            red[(r0 + 8) * 4 + wn] = rs1[mf];
        }
    }
    __syncthreads();
    if (tid < 128) {
        int mm = mBase + tid, il = mm >> 2, h = mm & 3;
        if (il < L) {
            float s4 = red[tid * 4] + red[tid * 4 + 1] + red[tid * 4 + 2] + red[tid * 4 + 3];
            g_inv[(size_t)(s0 + il) * NH + 4 * g + h] = 1.f / s4;
        }
    }
}

// ---------------- K2 (merged): delta (x<16, skips salient rows) || osal (x>=16) ----------------
__global__ void __launch_bounds__(256, 1) k_pv(const float* __restrict__ cc, float* __restrict__ outc) {
    extern __shared__ char dsm[];
    const int sg = blockIdx.y;
    const int s = sg >> 3, g = sg & 7;
    const int s0 = g_cu[s];
    const int L = g_cu[s + 1] - s0;
    const int salst = g_salst[s], salcnt = g_salcnt[s];

    const int tid = threadIdx.x, wid = tid >> 5, lane = tid & 31;
    const int wm = wid >> 2, wn = wid & 3;
    const uint32_t sb = smem_to_u32(dsm);
    const uint4 z4 = make_uint4(0, 0, 0, 0);

    float acc[4][4][4];
#pragma unroll
    for (int a = 0; a < 4; a++)
#pragma unroll
        for (int b = 0; b < 4; b++)
#pragma unroll
            for (int c = 0; c < 4; c++) acc[a][b][c] = 0.f;

    if (blockIdx.x < 16) {
        // ---------- delta: out = c_cache + inv * (Psal @ vdelta^T), skip salient rows ----------
        const int mBase = blockIdx.x * 128;
        if (mBase >= 4 * L) return;

#pragma unroll
        for (int it = 0; it < 8; it++) {
            int idx = tid + it * 256;
            int r = idx >> 4, ch = idx & 15;
            uint32_t d = (uint32_t)(r * 256) + (((uint32_t)(ch ^ (r & 7))) << 4);
            int mm = mBase + r, il = mm >> 2, hh = mm & 3;
            bool va = (il < L) && (ch * 8 < salcnt);
            size_t ia = ((size_t)(s0 + il) * NH + 4 * g + hh) * 128 + ch * 8;
            *(uint4*)(dsm + d)         = va ? *(const uint4*)(g_Psal_hi + ia) : z4;
            *(uint4*)(dsm + 32768 + d) = va ? *(const uint4*)(g_Psal_lo + ia) : z4;
            bool vb = (ch * 8 < salcnt);
            size_t ib = ((size_t)(g * HD + r)) * NSALT + salst + ch * 8;
            *(uint4*)(dsm + 65536 + d) = vb ? *(const uint4*)(g_vdT_hi + ib) : z4;
            *(uint4*)(dsm + 98304 + d) = vb ? *(const uint4*)(g_vdT_lo + ib) : z4;
        }
        __syncthreads();
        hmma_tile(sb, 0, 65536, acc, wid, lane);

#pragma unroll
        for (int mf = 0; mf < 4; mf++) {
            int mr0 = mBase + wm * 64 + mf * 16 + (lane >> 2);
            int mr1 = mr0 + 8;
            int il0 = mr0 >> 2, h0 = mr0 & 3;
            int il1 = mr1 >> 2, h1 = mr1 & 3;
            // skip salient rows: fully overwritten by osal half
            bool ok0 = (il0 < L) && (g_salpos[s0 + il0] < 0);
            bool ok1 = (il1 < L) && (g_salpos[s0 + il1] < 0);
            size_t id0 = (size_t)(s0 + il0) * NH + 4 * g + h0;
            size_t id1 = (size_t)(s0 + il1) * NH + 4 * g + h1;
            float inv0 = ok0 ? g_inv[id0] : 0.f;
            float inv1 = ok1 ? g_inv[id1] : 0.f;
#pragma unroll
            for (int nf = 0; nf < 4; nf++) {
                int dcol = wn * 32 + nf * 8 + (lane & 3) * 2;
                float* c = acc[mf][nf];
                if (ok0) {
                    size_t ob = id0 * HD + dcol;
                    float2 cv = *(const float2*)(cc + ob);
                    *(float2*)(outc + ob) = make_float2(cv.x + inv0 * c[0], cv.y + inv0 * c[1]);
                }
                if (ok1) {
                    size_t ob = id1 * HD + dcol;
                    float2 cv = *(const float2*)(cc + ob);
                    *(float2*)(outc + ob) = make_float2(cv.x + inv1 * c[2], cv.y + inv1 * c[3]);
                }
            }
        }
    } else {
        // ---------- osal: salient rows: out = inv * (P @ vnew^T) ----------
        const int mBase = (blockIdx.x - 16) * 128;
        if (mBase >= 4 * salcnt) return;

        for (int kc = 0; kc * 128 < L; kc++) {
#pragma unroll
            for (int it = 0; it < 8; it++) {
                int idx = tid + it * 256;
                int r = idx >> 4, ch = idx & 15;
                uint32_t d = (uint32_t)(r * 256) + (((uint32_t)(ch ^ (r & 7))) << 4);
                int m = mBase + r, saloc = m >> 2, hh = m & 3;
                int kk = kc * 128 + ch * 8;
                bool va = (saloc < salcnt) && (kk < L);
                size_t ia = ((size_t)(salst + saloc) * NH + 4 * g + hh) * SMAXK + kk;
                *(uint4*)(dsm + d)         = va ? *(const uint4*)(g_Posal_hi + ia) : z4;
                *(uint4*)(dsm + 32768 + d) = va ? *(const uint4*)(g_Posal_lo + ia) : z4;
                bool vb = (kk < L);
                size_t ib = ((size_t)(g * HD + r)) * TT + s0 + kk;
                *(uint4*)(dsm + 65536 + d) = vb ? *(const uint4*)(g_vnT_hi + ib) : z4;
                *(uint4*)(dsm + 98304 + d) = vb ? *(const uint4*)(g_vnT_lo + ib) : z4;
            }
            __syncthreads();
            hmma_tile(sb, 0, 65536, acc, wid, lane);
            __syncthreads();
        }

#pragma unroll
        for (int mf = 0; mf < 4; mf++) {
            int mr0 = mBase + wm * 64 + mf * 16 + (lane >> 2);
            int mr1 = mr0 + 8;
            int sa0 = mr0 >> 2, h0 = mr0 & 3;
            int sa1 = mr1 >> 2, h1 = mr1 & 3;
            bool ok0 = sa0 < salcnt, ok1 = sa1 < salcnt;
            size_t id0 = 0, id1 = 0;
            float inv0 = 0.f, inv1 = 0.f;
            if (ok0) { id0 = (size_t)g_idx[salst + sa0] * NH + 4 * g + h0; inv0 = g_inv[id0]; }
            if (ok1) { id1 = (size_t)g_idx[salst + sa1] * NH + 4 * g + h1; inv1 = g_inv[id1]; }
#pragma unroll
            for (int nf = 0; nf < 4; nf++) {
                int dcol = wn * 32 + nf * 8 + (lane & 3) * 2;
                float* c = acc[mf][nf];
                if (ok0) *(float2*)(outc + id0 * HD + dcol) = make_float2(inv0 * c[0], inv0 * c[1]);
                if (ok1) *(float2*)(outc + id1 * HD + dcol) = make_float2(inv1 * c[2], inv1 * c[3]);
            }
        }
    }
}

// ---------------- K3: per-row cosine similarity ----------------
__global__ void __launch_bounds__(256) k_cos(const float* __restrict__ cc, const float* __restrict__ outc,
                                             float* __restrict__ cosv) {
    __shared__ float sh[3][256];
    size_t base = (size_t)blockIdx.x * (NH * HD);
    const float4* a4 = (const float4*)(cc + base);
    const float4* b4 = (const float4*)(outc + base);
    float ab = 0.f, aa = 0.f, bb = 0.f;
    for (int j = threadIdx.x; j < (NH * HD) / 4; j += 256) {
        float4 x = a4[j], y = b4[j];
        ab += x.x * y.x + x.y * y.y + x.z * y.z + x.w * y.w;
        aa += x.x * x.x + x.y * x.y + x.z * x.z + x.w * x.w;
        bb += y.x * y.x + y.y * y.y + y.z * y.z + y.w * y.w;
    }
    sh[0][threadIdx.x] = ab; sh[1][threadIdx.x] = aa; sh[2][threadIdx.x] = bb;
    __syncthreads();
    for (int o = 128; o; o >>= 1) {
        if (threadIdx.x < o) {
            sh[0][threadIdx.x] += sh[0][threadIdx.x + o];
            sh[1][threadIdx.x] += sh[1][threadIdx.x + o];
            sh[2][threadIdx.x] += sh[2][threadIdx.x + o];
        }
        __syncthreads();
    }
    if (threadIdx.x == 0)
        cosv[blockIdx.x] = sh[0][0] / (sqrtf(sh[1][0]) * sqrtf(sh[2][0]) + 1e-8f);
}

// ---------------- launch ----------------
extern "C" void kernel_launch(void* const* d_in, const int* in_sizes, int n_in,
                              void* d_out, int out_size) {
    const float* q       = (const float*)d_in[0];
    const float* k       = (const float*)d_in[1];
    const float* v       = (const float*)d_in[2];
    const float* v_cache = (const float*)d_in[3];
    const float* c_cache = (const float*)d_in[4];
    const void*  idx     = d_in[5];
    const void*  cu      = d_in[6];

    float* outc = (float*)d_out;
    float* cosv = outc + (size_t)(out_size - TT);

    cudaFuncSetAttribute(k_qk,  cudaFuncAttributeMaxDynamicSharedMemorySize, 196608);
    cudaFuncSetAttribute(k_pv,  cudaFuncAttributeMaxDynamicSharedMemorySize, 131072);
    cudaFuncSetAttribute(k_pre, cudaFuncAttributeMaxDynamicSharedMemorySize, 16512);

    k_prep<<<1, 256>>>(idx, cu);
    k_pre<<<CVT_BLKS + VN_BLKS + VD_BLKS, 256, 16512>>>(q, k, v, v_cache);
    k_qk<<<dim3(16, 32), 256, 196608>>>();
    k_pv<<<dim3(20, 32), 256, 131072>>>(c_cache, outc);
    k_cos<<<TT, 256>>>(c_cache, outc, cosv);
}

// round 7
// speedup vs baseline: 2.2984x; 1.2061x over previous
#include <cuda_runtime.h>
#include <cuda_bf16.h>
#include <math.h>
#include <stdint.h>

typedef unsigned long long ull;
typedef long long ll;

#define TT    2048
#define NH    32
#define NKV   8
#define HD    128
#define NSALT 512
#define NSEG  4
#define SMAXK 512
#define SCALE_F 0.08838834764831845f

#define CVT_BLKS 10240
#define VN_BLKS  512
#define VD_BLKS  128

// smem layout for 64-row tiles (dynamic, 96KB):
//   A_hi: [0, 16K)  A_lo: [16K, 32K)  B_hi: [32K, 64K)  B_lo: [64K, 96K)
#define A_LO 16384u
#define B_HI 32768u
#define B_LO 32768u   // relative to B_HI base

// ---------------- scratch (device globals: allocation-free) ----------------
__device__ float g_inv[(size_t)TT * NH];
__device__ __nv_bfloat16 g_qhi[(size_t)TT * NH * HD];
__device__ __nv_bfloat16 g_qlo[(size_t)TT * NH * HD];
__device__ __nv_bfloat16 g_khi[(size_t)TT * NKV * HD];
__device__ __nv_bfloat16 g_klo[(size_t)TT * NKV * HD];
__device__ __nv_bfloat16 g_Psal_hi[(size_t)TT * NH * 128];
__device__ __nv_bfloat16 g_Psal_lo[(size_t)TT * NH * 128];
__device__ __nv_bfloat16 g_Posal_hi[(size_t)NSALT * NH * SMAXK];
__device__ __nv_bfloat16 g_Posal_lo[(size_t)NSALT * NH * SMAXK];
__device__ __nv_bfloat16 g_vnT_hi[(size_t)NKV * HD * TT];
__device__ __nv_bfloat16 g_vnT_lo[(size_t)NKV * HD * TT];
__device__ __nv_bfloat16 g_vdT_hi[(size_t)NKV * HD * NSALT];
__device__ __nv_bfloat16 g_vdT_lo[(size_t)NKV * HD * NSALT];
__device__ int   g_idx[NSALT];
__device__ int   g_cu[NSEG + 1];
__device__ int   g_salpos[TT];
__device__ int   g_salst[NSEG];
__device__ int   g_salcnt[NSEG];

// ---------------- helpers ----------------
__device__ __forceinline__ uint32_t smem_to_u32(const void* p) {
    uint32_t a;
    asm("{ .reg .u64 t; cvta.to.shared.u64 t, %1; cvt.u32.u64 %0, t; }" : "=r"(a) : "l"(p));
    return a;
}
__device__ __forceinline__ void ldsm4(uint32_t* r, uint32_t addr) {
    asm volatile("ldmatrix.sync.aligned.m8n8.x4.shared.b16 {%0,%1,%2,%3}, [%4];"
        : "=r"(r[0]), "=r"(r[1]), "=r"(r[2]), "=r"(r[3]) : "r"(addr));
}
__device__ __forceinline__ void mma16816(float* c, const uint32_t* a, uint32_t b0, uint32_t b1) {
    asm volatile("mma.sync.aligned.m16n8k16.row.col.f32.bf16.bf16.f32 "
        "{%0,%1,%2,%3}, {%4,%5,%6,%7}, {%8,%9}, {%0,%1,%2,%3};"
        : "+f"(c[0]), "+f"(c[1]), "+f"(c[2]), "+f"(c[3])
        : "r"(a[0]), "r"(a[1]), "r"(a[2]), "r"(a[3]), "r"(b0), "r"(b1));
}
__device__ __forceinline__ void cpa16(uint32_t dst, const void* src, bool valid) {
    int sz = valid ? 16 : 0;
    asm volatile("cp.async.cg.shared.global [%0], [%1], 16, %2;"
        :: "r"(dst), "l"(src), "r"(sz) : "memory");
}
#define CP_COMMIT() asm volatile("cp.async.commit_group;" ::: "memory")
#define CP_WAIT0()  asm volatile("cp.async.wait_group 0;" ::: "memory")

// 64(m)x128(n)x128(k) bf16 3-pass HMMA tile. Rows 256B, 16B-chunk XOR swizzle.
// 8 warps = 2(m) x 4(n); warp tile 32x32. acc[2][4][4].
__device__ __forceinline__ void hmma_tile64(uint32_t sb, float acc[2][4][4], int wid, int lane) {
    const int wm = wid >> 2, wn = wid & 3;
    uint32_t a_ad[2], a_rx[2];
#pragma unroll
    for (int mf = 0; mf < 2; mf++) {
        int row = wm * 32 + mf * 16 + (lane & 15);
        a_ad[mf] = sb + row * 256;
        a_rx[mf] = ((uint32_t)(row & 7)) << 4;
    }
    const int achunk = (lane >> 4);
    uint32_t b_ad[2], b_rx[2];
#pragma unroll
    for (int bg = 0; bg < 2; bg++) {
        int n = wn * 32 + bg * 16 + (lane & 7) + ((lane >> 4) << 3);
        b_ad[bg] = sb + B_HI + n * 256;
        b_rx[bg] = ((uint32_t)(n & 7)) << 4;
    }
    const int bchunk = (lane >> 3) & 1;

#pragma unroll
    for (int ks = 0; ks < 8; ks++) {
        uint32_t ah[2][4], al[2][4];
#pragma unroll
        for (int mf = 0; mf < 2; mf++) {
            uint32_t coff = (((uint32_t)(ks * 2 + achunk)) << 4) ^ a_rx[mf];
            ldsm4(ah[mf], a_ad[mf] + coff);
            ldsm4(al[mf], a_ad[mf] + A_LO + coff);
        }
        uint32_t bh[2][4], bl[2][4];
#pragma unroll
        for (int bg = 0; bg < 2; bg++) {
            uint32_t coff = (((uint32_t)(ks * 2 + bchunk)) << 4) ^ b_rx[bg];
            ldsm4(bh[bg], b_ad[bg] + coff);
            ldsm4(bl[bg], b_ad[bg] + B_LO + coff);
        }
#pragma unroll
        for (int mf = 0; mf < 2; mf++)
#pragma unroll
            for (int nf = 0; nf < 4; nf++) {
                int bg = nf >> 1, sel = (nf & 1) * 2;
                mma16816(acc[mf][nf], ah[mf], bh[bg][sel], bh[bg][sel + 1]);
                mma16816(acc[mf][nf], ah[mf], bl[bg][sel], bl[bg][sel + 1]);
                mma16816(acc[mf][nf], al[mf], bh[bg][sel], bh[bg][sel + 1]);
            }
    }
}

__device__ __forceinline__ void bf_split(float x, __nv_bfloat16& h, __nv_bfloat16& l) {
    h = __float2bfloat16(x);
    l = __float2bfloat16(x - __bfloat162float(h));
}

// ---------------- K0a: decode indices, segment tables ----------------
__global__ void k_prep(const void* idx_raw, const void* cu_raw) {
    const int* i32 = (const int*)idx_raw;
    const int* c32 = (const int*)cu_raw;
    const bool idx64 = (i32[1] == 0);
    const bool cu64  = (c32[1] == 0);
    const int t = threadIdx.x;

    for (int i = t; i < NSALT; i += 256)
        g_idx[i] = idx64 ? (int)((const long long*)idx_raw)[i] : i32[i];
    if (t <= NSEG)
        g_cu[t] = cu64 ? (int)((const long long*)cu_raw)[t] : c32[t];
    for (int i = t; i < TT; i += 256) g_salpos[i] = -1;
    __syncthreads();
    for (int i = t; i < NSALT; i += 256) g_salpos[g_idx[i]] = i;
    if (t == 0) {
        for (int s = 0; s < NSEG; s++) {
            int a = 0;
            while (a < NSALT && g_idx[a] < g_cu[s]) a++;
            int b = a;
            while (b < NSALT && g_idx[b] < g_cu[s + 1]) b++;
            g_salst[s] = a;
            g_salcnt[s] = b - a;
        }
    }
}

// ---------------- K0b (merged): cvt || build_vn || build_vd ----------------
__global__ void __launch_bounds__(256) k_pre(const float* __restrict__ q, const float* __restrict__ kk,
                                             const float* __restrict__ v, const float* __restrict__ vc) {
    extern __shared__ float tile[];   // [32][129]
    const int bx = blockIdx.x;
    const int tid = threadIdx.x;

    if (bx < CVT_BLKS) {
        const int nq4 = TT * NH * HD / 4;
        int i = bx * 256 + tid;
        float4 x;
        __nv_bfloat162 *h2, *l2;
        if (i < nq4) {
            x = ((const float4*)q)[i];
            h2 = (__nv_bfloat162*)g_qhi + 2 * (size_t)i;
            l2 = (__nv_bfloat162*)g_qlo + 2 * (size_t)i;
        } else {
            int j = i - nq4;
            x = ((const float4*)kk)[j];
            h2 = (__nv_bfloat162*)g_khi + 2 * (size_t)j;
            l2 = (__nv_bfloat162*)g_klo + 2 * (size_t)j;
        }
        __nv_bfloat162 a = __float22bfloat162_rn(make_float2(x.x, x.y));
        __nv_bfloat162 b = __float22bfloat162_rn(make_float2(x.z, x.w));
        __nv_bfloat162 al = __float22bfloat162_rn(make_float2(x.x - __low2float(a), x.y - __high2float(a)));
        __nv_bfloat162 bl = __float22bfloat162_rn(make_float2(x.z - __low2float(b), x.w - __high2float(b)));
        h2[0] = a; h2[1] = b; l2[0] = al; l2[1] = bl;
        return;
    }

    if (bx < CVT_BLKS + VN_BLKS) {
        int t2 = bx - CVT_BLKS;
        int kc = t2 >> 3, g = t2 & 7;
#pragma unroll
        for (int it = 0; it < 4; it++) {
            int fi = tid + it * 256;
            int key = fi >> 5, c4 = fi & 31;
            int gk = kc * 32 + key;
            int sp = g_salpos[gk];
            const float* src = (sp >= 0) ? v + ((size_t)sp * NKV + g) * HD + c4 * 4
                                         : vc + ((size_t)gk * NKV + g) * HD + c4 * 4;
            float4 x = *(const float4*)src;
            float* tr = tile + key * 129 + c4 * 4;
            tr[0] = x.x; tr[1] = x.y; tr[2] = x.z; tr[3] = x.w;
        }
        __syncthreads();
#pragma unroll
        for (int it = 0; it < 8; it++) {
            int wi = tid + it * 256;
            int d = wi >> 4, kp = wi & 15;
            float v0 = tile[(2 * kp) * 129 + d], v1 = tile[(2 * kp + 1) * 129 + d];
            __nv_bfloat16 h0, l0, h1, l1;
            bf_split(v0, h0, l0); bf_split(v1, h1, l1);
            __nv_bfloat162 ph; ph.x = h0; ph.y = h1;
            __nv_bfloat162 pl; pl.x = l0; pl.y = l1;
            size_t dst = ((size_t)g * HD + d) * TT + kc * 32 + 2 * kp;
            *(__nv_bfloat162*)(g_vnT_hi + dst) = ph;
            *(__nv_bfloat162*)(g_vnT_lo + dst) = pl;
        }
        return;
    }

    {
        int t2 = bx - CVT_BLKS - VN_BLKS;
        int kc = t2 >> 3, g = t2 & 7;
#pragma unroll
        for (int it = 0; it < 4; it++) {
            int fi = tid + it * 256;
            int sidx = fi >> 5, c4 = fi & 31;
            int sal = kc * 32 + sidx;
            const float* pv = v  + ((size_t)sal * NKV + g) * HD + c4 * 4;
            const float* pc = vc + ((size_t)g_idx[sal] * NKV + g) * HD + c4 * 4;
            float4 a = *(const float4*)pv;
            float4 b = *(const float4*)pc;
            float* tr = tile + sidx * 129 + c4 * 4;
            tr[0] = a.x - b.x; tr[1] = a.y - b.y; tr[2] = a.z - b.z; tr[3] = a.w - b.w;
        }
        __syncthreads();
#pragma unroll
        for (int it = 0; it < 8; it++) {
            int wi = tid + it * 256;
            int d = wi >> 4, kp = wi & 15;
            float v0 = tile[(2 * kp) * 129 + d], v1 = tile[(2 * kp + 1) * 129 + d];
            __nv_bfloat16 h0, l0, h1, l1;
            bf_split(v0, h0, l0); bf_split(v1, h1, l1);
            __nv_bfloat162 ph; ph.x = h0; ph.y = h1;
            __nv_bfloat162 pl; pl.x = l0; pl.y = l1;
            size_t dst = ((size_t)g * HD + d) * NSALT + kc * 32 + 2 * kp;
            *(__nv_bfloat162*)(g_vdT_hi + dst) = ph;
            *(__nv_bfloat162*)(g_vdT_lo + dst) = pl;
        }
    }
}

// ---------------- K1: fused QK^T + exp + rowsum, 64-row tiles, 2 CTAs/SM ----------------
__global__ void __launch_bounds__(256, 2) k_qk() {
    extern __shared__ char dsm[];
    __shared__ int s_sp[SMAXK];
    const int sg = blockIdx.y;
    const int s = sg >> 3, g = sg & 7;
    const int s0 = g_cu[s];
    const int L = g_cu[s + 1] - s0;
    const int mBase = blockIdx.x * 64;
    if (mBase >= 4 * L) return;
    const int salst = g_salst[s];

    const int tid = threadIdx.x, wid = tid >> 5, lane = tid & 31;
    const int wm = wid >> 2, wn = wid & 3;
    const uint32_t sb = smem_to_u32(dsm);

    for (int j = tid; j < L; j += 256) {
        int sp = g_salpos[s0 + j];
        s_sp[j] = sp >= 0 ? sp - salst : -1;
    }

    // A tile: 64 rows, hi/lo
#pragma unroll
    for (int it = 0; it < 4; it++) {
        int idx = tid + it * 256;
        int r = idx >> 4, ch = idx & 15;
        uint32_t d = (uint32_t)(r * 256) + (((uint32_t)(ch ^ (r & 7))) << 4);
        int mm = mBase + r, il = mm >> 2, hh = mm & 3;
        bool v = il < L;
        size_t o = v ? (((size_t)(s0 + il) * NH + 4 * g + hh) * HD + ch * 8) : 0;
        cpa16(sb + d, g_qhi + o, v);
        cpa16(sb + A_LO + d, g_qlo + o, v);
    }

    // per-row metadata
    size_t id0[2], id1[2];
    ll pb0[2], pb1[2];
    bool ok0[2], ok1[2];
#pragma unroll
    for (int mf = 0; mf < 2; mf++) {
        int mr0 = mBase + wm * 32 + mf * 16 + (lane >> 2);
        int mr1 = mr0 + 8;
        int il0 = mr0 >> 2, h0 = mr0 & 3;
        int il1 = mr1 >> 2, h1 = mr1 & 3;
        ok0[mf] = il0 < L; ok1[mf] = il1 < L;
        id0[mf] = ok0[mf] ? ((size_t)(s0 + il0) * NH + 4 * g + h0) : 0;
        id1[mf] = ok1[mf] ? ((size_t)(s0 + il1) * NH + 4 * g + h1) : 0;
        int sp0 = ok0[mf] ? g_salpos[s0 + il0] : -1;
        int sp1 = ok1[mf] ? g_salpos[s0 + il1] : -1;
        pb0[mf] = sp0 >= 0 ? ((ll)sp0 * NH + 4 * g + h0) * SMAXK : -1;
        pb1[mf] = sp1 >= 0 ? ((ll)sp1 * NH + 4 * g + h1) * SMAXK : -1;
    }

    float rs0[2] = {0.f, 0.f}, rs1[2] = {0.f, 0.f};

    for (int nt = 0; nt < 4; nt++) {
        // B tile for this nt
#pragma unroll
        for (int it = 0; it < 8; it++) {
            int idx = tid + it * 256;
            int r = idx >> 4, ch = idx & 15;
            uint32_t d = (uint32_t)(r * 256) + (((uint32_t)(ch ^ (r & 7))) << 4);
            int jg = nt * 128 + r;
            bool v = jg < L;
            size_t o = v ? (((size_t)(s0 + jg) * NKV + g) * HD + ch * 8) : 0;
            cpa16(sb + B_HI + d, g_khi + o, v);
            cpa16(sb + B_HI + B_LO + d, g_klo + o, v);
        }
        CP_COMMIT();
        CP_WAIT0();
        __syncthreads();

        float acc[2][4][4];
#pragma unroll
        for (int a = 0; a < 2; a++)
#pragma unroll
            for (int b = 0; b < 4; b++)
#pragma unroll
                for (int c = 0; c < 4; c++) acc[a][b][c] = 0.f;

        hmma_tile64(sb, acc, wid, lane);
        __syncthreads();

#pragma unroll
        for (int nf = 0; nf < 4; nf++) {
            int col = nt * 128 + wn * 32 + nf * 8 + (lane & 3) * 2;
            bool c0 = col < L, c1 = col + 1 < L;
            int spa = c0 ? s_sp[col] : -1;
            int spb = c1 ? s_sp[col + 1] : -1;
#pragma unroll
            for (int mf = 0; mf < 2; mf++) {
                float* c = acc[mf][nf];
                float e0 = (ok0[mf] && c0) ? __expf(c[0] * SCALE_F) : 0.f;
                float e1 = (ok0[mf] && c1) ? __expf(c[1] * SCALE_F) : 0.f;
                float e2 = (ok1[mf] && c0) ? __expf(c[2] * SCALE_F) : 0.f;
                float e3 = (ok1[mf] && c1) ? __expf(c[3] * SCALE_F) : 0.f;
                rs0[mf] += e0 + e1;
                rs1[mf] += e2 + e3;

                if (spa >= 0) {
                    if (ok0[mf]) { __nv_bfloat16 h, l; bf_split(e0, h, l);
                        g_Psal_hi[id0[mf] * 128 + spa] = h; g_Psal_lo[id0[mf] * 128 + spa] = l; }
                    if (ok1[mf]) { __nv_bfloat16 h, l; bf_split(e2, h, l);
                        g_Psal_hi[id1[mf] * 128 + spa] = h; g_Psal_lo[id1[mf] * 128 + spa] = l; }
                }
                if (spb >= 0) {
                    if (ok0[mf]) { __nv_bfloat16 h, l; bf_split(e1, h, l);
                        g_Psal_hi[id0[mf] * 128 + spb] = h; g_Psal_lo[id0[mf] * 128 + spb] = l; }
                    if (ok1[mf]) { __nv_bfloat16 h, l; bf_split(e3, h, l);
                        g_Psal_hi[id1[mf] * 128 + spb] = h; g_Psal_lo[id1[mf] * 128 + spb] = l; }
                }
                if (pb0[mf] >= 0 && c0) {
                    __nv_bfloat16 h0, l0, h1, l1;
                    bf_split(e0, h0, l0); bf_split(e1, h1, l1);
                    __nv_bfloat162 ph; ph.x = h0; ph.y = h1;
                    __nv_bfloat162 pl; pl.x = l0; pl.y = l1;
                    *(__nv_bfloat162*)(g_Posal_hi + pb0[mf] + col) = ph;
                    *(__nv_bfloat162*)(g_Posal_lo + pb0[mf] + col) = pl;
                }
                if (pb1[mf] >= 0 && c0) {
                    __nv_bfloat16 h0, l0, h1, l1;
                    bf_split(e2, h0, l0); bf_split(e3, h1, l1);
                    __nv_bfloat162 ph; ph.x = h0; ph.y = h1;
                    __nv_bfloat162 pl; pl.x = l0; pl.y = l1;
                    *(__nv_bfloat162*)(g_Posal_hi + pb1[mf] + col) = ph;
                    *(__nv_bfloat162*)(g_Posal_lo + pb1[mf] + col) = pl;
                }
            }
        }
    }

    // final rowsum reduction -> g_inv (reuse A region)
#pragma unroll
    for (int mf = 0; mf < 2; mf++) {
        rs0[mf] += __shfl_xor_sync(0xffffffffu, rs0[mf], 1);
        rs0[mf] += __shfl_xor_sync(0xffffffffu, rs0[mf], 2);
        rs1[mf] += __shfl_xor_sync(0xffffffffu, rs1[mf], 1);
        rs1[mf] += __shfl_xor_sync(0xffffffffu, rs1[mf], 2);
    }
    __syncthreads();
    float* red = (float*)dsm;
    if ((lane & 3) == 0) {
#pragma unroll
        for (int mf = 0; mf < 2; mf++) {
            int r0 = wm * 32 + mf * 16 + (lane >> 2);
            red[r0 * 4 + wn] = rs0[mf];
            red[(r0 + 8) * 4 + wn] = rs1[mf];
        }
    }
    __syncthreads();
    if (tid < 64) {
        int mm = mBase + tid, il = mm >> 2, h = mm & 3;
        if (il < L) {
            float s4 = red[tid * 4] + red[tid * 4 + 1] + red[tid * 4 + 2] + red[tid * 4 + 3];
            g_inv[(size_t)(s0 + il) * NH + 4 * g + h] = 1.f / s4;
        }
    }
}

// ---------------- K2 (merged): osal (x<8) || delta (x>=8), 64-row tiles ----------------
__global__ void __launch_bounds__(256, 2) k_pv(const float* __restrict__ cc, float* __restrict__ outc) {
    extern __shared__ char dsm[];
    const int sg = blockIdx.y;
    const int s = sg >> 3, g = sg & 7;
    const int s0 = g_cu[s];
    const int L = g_cu[s + 1] - s0;
    const int salst = g_salst[s], salcnt = g_salcnt[s];

    const int tid = threadIdx.x, wid = tid >> 5, lane = tid & 31;
    const int wm = wid >> 2, wn = wid & 3;
    const uint32_t sb = smem_to_u32(dsm);

    float acc[2][4][4];
#pragma unroll
    for (int a = 0; a < 2; a++)
#pragma unroll
        for (int b = 0; b < 4; b++)
#pragma unroll
            for (int c = 0; c < 4; c++) acc[a][b][c] = 0.f;

    if (blockIdx.x < 8) {
        // ---------- osal: salient rows: out = inv * (P @ vnew^T) ----------
        const int mBase = blockIdx.x * 64;
        if (mBase >= 4 * salcnt) return;

        for (int kc = 0; kc * 128 < L; kc++) {
#pragma unroll
            for (int it = 0; it < 4; it++) {
                int idx = tid + it * 256;
                int r = idx >> 4, ch = idx & 15;
                uint32_t d = (uint32_t)(r * 256) + (((uint32_t)(ch ^ (r & 7))) << 4);
                int m = mBase + r, saloc = m >> 2, hh = m & 3;
                int kk = kc * 128 + ch * 8;
                bool va = (saloc < salcnt) && (kk < L);
                size_t ia = va ? (((size_t)(salst + saloc) * NH + 4 * g + hh) * SMAXK + kk) : 0;
                cpa16(sb + d, g_Posal_hi + ia, va);
                cpa16(sb + A_LO + d, g_Posal_lo + ia, va);
            }
#pragma unroll
            for (int it = 0; it < 8; it++) {
                int idx = tid + it * 256;
                int r = idx >> 4, ch = idx & 15;
                uint32_t d = (uint32_t)(r * 256) + (((uint32_t)(ch ^ (r & 7))) << 4);
                int kk = kc * 128 + ch * 8;
                bool vb = (kk < L);
                size_t ib = vb ? (((size_t)(g * HD + r)) * TT + s0 + kk) : 0;
                cpa16(sb + B_HI + d, g_vnT_hi + ib, vb);
                cpa16(sb + B_HI + B_LO + d, g_vnT_lo + ib, vb);
            }
            CP_COMMIT();
            CP_WAIT0();
            __syncthreads();
            hmma_tile64(sb, acc, wid, lane);
            __syncthreads();
        }

#pragma unroll
        for (int mf = 0; mf < 2; mf++) {
            int mr0 = mBase + wm * 32 + mf * 16 + (lane >> 2);
            int mr1 = mr0 + 8;
            int sa0 = mr0 >> 2, h0 = mr0 & 3;
            int sa1 = mr1 >> 2, h1 = mr1 & 3;
            bool ok0 = sa0 < salcnt, ok1 = sa1 < salcnt;
            size_t id0 = 0, id1 = 0;
            float inv0 = 0.f, inv1 = 0.f;
            if (ok0) { id0 = (size_t)g_idx[salst + sa0] * NH + 4 * g + h0; inv0 = g_inv[id0]; }
            if (ok1) { id1 = (size_t)g_idx[salst + sa1] * NH + 4 * g + h1; inv1 = g_inv[id1]; }
#pragma unroll
            for (int nf = 0; nf < 4; nf++) {
                int dcol = wn * 32 + nf * 8 + (lane & 3) * 2;
                float* c = acc[mf][nf];
                if (ok0) *(float2*)(outc + id0 * HD + dcol) = make_float2(inv0 * c[0], inv0 * c[1]);
                if (ok1) *(float2*)(outc + id1 * HD + dcol) = make_float2(inv1 * c[2], inv1 * c[3]);
            }
        }
    } else {
        // ---------- delta: out = c_cache + inv * (Psal @ vdelta^T), skip salient rows ----------
        const int mBase = (blockIdx.x - 8) * 64;
        if (mBase >= 4 * L) return;

#pragma unroll
        for (int it = 0; it < 4; it++) {
            int idx = tid + it * 256;
            int r = idx >> 4, ch = idx & 15;
            uint32_t d = (uint32_t)(r * 256) + (((uint32_t)(ch ^ (r & 7))) << 4);
            int mm = mBase + r, il = mm >> 2, hh = mm & 3;
            bool va = (il < L) && (ch * 8 < salcnt);
            size_t ia = va ? (((size_t)(s0 + il) * NH + 4 * g + hh) * 128 + ch * 8) : 0;
            cpa16(sb + d, g_Psal_hi + ia, va);
            cpa16(sb + A_LO + d, g_Psal_lo + ia, va);
        }
#pragma unroll
        for (int it = 0; it < 8; it++) {
            int idx = tid + it * 256;
            int r = idx >> 4, ch = idx & 15;
            uint32_t d = (uint32_t)(r * 256) + (((uint32_t)(ch ^ (r & 7))) << 4);
            bool vb = (ch * 8 < salcnt);
            size_t ib = vb ? (((size_t)(g * HD + r)) * NSALT + salst + ch * 8) : 0;
            cpa16(sb + B_HI + d, g_vdT_hi + ib, vb);
            cpa16(sb + B_HI + B_LO + d, g_vdT_lo + ib, vb);
        }
        CP_COMMIT();
        CP_WAIT0();
        __syncthreads();
        hmma_tile64(sb, acc, wid, lane);

#pragma unroll
        for (int mf = 0; mf < 2; mf++) {
            int mr0 = mBase + wm * 32 + mf * 16 + (lane >> 2);
            int mr1 = mr0 + 8;
            int il0 = mr0 >> 2, h0 = mr0 & 3;
            int il1 = mr1 >> 2, h1 = mr1 & 3;
            bool ok0 = (il0 < L) && (g_salpos[s0 + il0] < 0);
            bool ok1 = (il1 < L) && (g_salpos[s0 + il1] < 0);
            size_t id0 = (size_t)(s0 + il0) * NH + 4 * g + h0;
            size_t id1 = (size_t)(s0 + il1) * NH + 4 * g + h1;
            float inv0 = ok0 ? g_inv[id0] : 0.f;
            float inv1 = ok1 ? g_inv[id1] : 0.f;
#pragma unroll
            for (int nf = 0; nf < 4; nf++) {
                int dcol = wn * 32 + nf * 8 + (lane & 3) * 2;
                float* c = acc[mf][nf];
                if (ok0) {
                    size_t ob = id0 * HD + dcol;
                    float2 cv = *(const float2*)(cc + ob);
                    *(float2*)(outc + ob) = make_float2(cv.x + inv0 * c[0], cv.y + inv0 * c[1]);
                }
                if (ok1) {
                    size_t ob = id1 * HD + dcol;
                    float2 cv = *(const float2*)(cc + ob);
                    *(float2*)(outc + ob) = make_float2(cv.x + inv1 * c[2], cv.y + inv1 * c[3]);
                }
            }
        }
    }
}

// ---------------- K3: per-row cosine similarity ----------------
__global__ void __launch_bounds__(256) k_cos(const float* __restrict__ cc, const float* __restrict__ outc,
                                             float* __restrict__ cosv) {
    __shared__ float sh[3][256];
    size_t base = (size_t)blockIdx.x * (NH * HD);
    const float4* a4 = (const float4*)(cc + base);
    const float4* b4 = (const float4*)(outc + base);
    float ab = 0.f, aa = 0.f, bb = 0.f;
    for (int j = threadIdx.x; j < (NH * HD) / 4; j += 256) {
        float4 x = a4[j], y = b4[j];
        ab += x.x * y.x + x.y * y.y + x.z * y.z + x.w * y.w;
        aa += x.x * x.x + x.y * x.y + x.z * x.z + x.w * x.w;
        bb += y.x * y.x + y.y * y.y + y.z * y.z + y.w * y.w;
    }
    sh[0][threadIdx.x] = ab; sh[1][threadIdx.x] = aa; sh[2][threadIdx.x] = bb;
    __syncthreads();
    for (int o = 128; o; o >>= 1) {
        if (threadIdx.x < o) {
            sh[0][threadIdx.x] += sh[0][threadIdx.x + o];
            sh[1][threadIdx.x] += sh[1][threadIdx.x + o];
            sh[2][threadIdx.x] += sh[2][threadIdx.x + o];
        }
        __syncthreads();
    }
    if (threadIdx.x == 0)
        cosv[blockIdx.x] = sh[0][0] / (sqrtf(sh[1][0]) * sqrtf(sh[2][0]) + 1e-8f);
}

// ---------------- launch ----------------
extern "C" void kernel_launch(void* const* d_in, const int* in_sizes, int n_in,
                              void* d_out, int out_size) {
    const float* q       = (const float*)d_in[0];
    const float* k       = (const float*)d_in[1];
    const float* v       = (const float*)d_in[2];
    const float* v_cache = (const float*)d_in[3];
    const float* c_cache = (const float*)d_in[4];
    const void*  idx     = d_in[5];
    const void*  cu      = d_in[6];

    float* outc = (float*)d_out;
    float* cosv = outc + (size_t)(out_size - TT);

    cudaFuncSetAttribute(k_qk,  cudaFuncAttributeMaxDynamicSharedMemorySize, 98304);
    cudaFuncSetAttribute(k_pv,  cudaFuncAttributeMaxDynamicSharedMemorySize, 98304);
    cudaFuncSetAttribute(k_pre, cudaFuncAttributeMaxDynamicSharedMemorySize, 16512);

    k_prep<<<1, 256>>>(idx, cu);
    k_pre<<<CVT_BLKS + VN_BLKS + VD_BLKS, 256, 16512>>>(q, k, v, v_cache);
    k_qk<<<dim3(32, 32), 256, 98304>>>();
    k_pv<<<dim3(40, 32), 256, 98304>>>(c_cache, outc);
    k_cos<<<TT, 256>>>(c_cache, outc, cosv);
}